// round 9
// baseline (speedup 1.0000x reference)
#include <cuda_runtime.h>
#include <cuda_fp16.h>
#include <math_constants.h>

#define NUM_CODES 2560
#define DIM       128
#define N_TOKENS  65536
#define TOT_ELEMS 8388608
#define TPC       256
#define CPC       64
#define N_CHUNKS  40
#define NSTAGE    3

#define RS          272
#define STAGE_B     (64 * RS)
#define OFF_BST     0
#define OFF_EN      69632                  // 256*RS (A temp) dominates 3*STAGE_B
#define OFF_ZN      (OFF_EN + NUM_CODES * 4)
#define SMEM_TENSOR (OFF_ZN + 1024)

__device__ __align__(16) float  g_enorm[NUM_CODES];
__device__ __align__(16) __half g_wh16[NUM_CODES * DIM];   // fp16(w * 4096)
__device__ int    g_enmax_i = 0;
__device__ int    g_inds[N_TOKENS];
__device__ int    g_listA[N_TOKENS];
__device__ int    g_i2a[N_TOKENS];
__device__ int    g_i3a[N_TOKENS];
__device__ int    g_listB[N_TOKENS];
__device__ int    g_nA, g_nB;
__device__ double g_s1, g_s3;

// ---------- helpers ----------
__device__ __forceinline__ unsigned smem_u32(const void* p) {
    unsigned a;
    asm("{ .reg .u64 t; cvta.to.shared.u64 t, %1; cvt.u32.u64 %0, t; }" : "=r"(a) : "l"(p));
    return a;
}
__device__ __forceinline__ unsigned lds32(unsigned a) {
    unsigned v;
    asm volatile("ld.shared.b32 %0, [%1];" : "=r"(v) : "r"(a));
    return v;
}
__device__ __forceinline__ float2 lds64f(unsigned a) {
    float2 v;
    asm volatile("ld.shared.v2.f32 {%0, %1}, [%2];" : "=f"(v.x), "=f"(v.y) : "r"(a));
    return v;
}
__device__ __forceinline__ void mma_f16(float* c, const unsigned* a,
                                        unsigned b0, unsigned b1) {
    asm volatile(
        "mma.sync.aligned.m16n8k16.row.col.f32.f16.f16.f32 "
        "{%0,%1,%2,%3}, {%4,%5,%6,%7}, {%8,%9}, {%0,%1,%2,%3};"
        : "+f"(c[0]), "+f"(c[1]), "+f"(c[2]), "+f"(c[3])
        : "r"(a[0]), "r"(a[1]), "r"(a[2]), "r"(a[3]), "r"(b0), "r"(b1));
}

// ---------- prep: enorm (+max) + fp16(w*4096) ----------
__global__ void vq_prep(const float* __restrict__ w) {
    int gtid = blockIdx.x * blockDim.x + threadIdx.x;
    if (gtid == 0) { g_s1 = 0.0; g_s3 = 0.0; g_nA = 0; g_nB = 0; }
    int gw = gtid >> 5, lane = threadIdx.x & 31;
    if (gw < NUM_CODES) {
        const float* row = w + (size_t)gw * DIM;
        float s = 0.0f;
        #pragma unroll
        for (int k = lane; k < DIM; k += 32) {
            float v = row[k];
            s = __fadd_rn(s, __fmul_rn(v, v));
        }
        #pragma unroll
        for (int off = 16; off > 0; off >>= 1) s += __shfl_xor_sync(~0u, s, off);
        if (lane == 0) {
            g_enorm[gw] = s;
            atomicMax(&g_enmax_i, __float_as_int(s));
        }
    }
    int stride = gridDim.x * blockDim.x;
    for (int i = gtid; i < NUM_CODES * DIM; i += stride)
        g_wh16[i] = __float2half_rn(w[i] * 4096.0f);
}

// ---------- tensor pass ----------
__device__ __forceinline__ void issue_chunk(unsigned sb, int tid, int cn, int st) {
    const uint4* gh = ((const uint4*)g_wh16) + (size_t)cn * 1024;
    unsigned base = sb + OFF_BST + st * STAGE_B;
    #pragma unroll
    for (int i = 0; i < 4; i++) {
        int f = tid + i * 256;
        unsigned d = base + (f >> 4) * RS + (f & 15) * 16;
        asm volatile("cp.async.cg.shared.global [%0], [%1], 16;" :: "r"(d), "l"(gh + f));
    }
}

__global__ void __launch_bounds__(256, 1)
vq_tensor(const float* __restrict__ batch) {
    extern __shared__ char smem[];
    const unsigned sb = smem_u32(smem);
    float* zn_s = (float*)(smem + OFF_ZN);

    const int tid = threadIdx.x, wid = tid >> 5, lane = tid & 31;
    const int n0 = blockIdx.x * TPC, b = n0 >> 12, hw0 = n0 & 4095;
    const float* zbase = batch + (size_t)b * (DIM * 4096) + hw0;
    const float enmax = __int_as_float(g_enmax_i);

    {
        const float* zp = zbase + tid;
        float acc = 0.0f;
        #pragma unroll 4
        for (int c = 0; c < DIM; c += 2) {
            float z0 = zp[(size_t)c * 4096];
            float z1 = zp[(size_t)(c + 1) * 4096];
            acc = __fadd_rn(acc, __fmul_rn(z0, z0));
            acc = __fadd_rn(acc, __fmul_rn(z1, z1));
            __half h0 = __float2half_rn(z0 * 16.0f);
            __half h1 = __float2half_rn(z1 * 16.0f);
            unsigned hp = (unsigned)__half_as_ushort(h0) |
                          ((unsigned)__half_as_ushort(h1) << 16);
            *(unsigned*)(smem + OFF_BST + tid * RS + c * 2) = hp;
        }
        zn_s[tid] = acc;
    }
    for (int i = tid; i < NUM_CODES; i += 256)
        ((float*)(smem + OFF_EN))[i] = g_enorm[i];
    __syncthreads();

    const unsigned Rb = wid * 32 + (lane >> 2);
    const unsigned Cb = (lane & 3) * 2;
    unsigned Ah[2][8][4];
    #pragma unroll
    for (int mt = 0; mt < 2; mt++)
        #pragma unroll
        for (int ks = 0; ks < 8; ks++) {
            unsigned a = sb + OFF_BST + (Rb + mt * 16) * RS + (ks * 16 + Cb) * 2;
            Ah[mt][ks][0] = lds32(a);
            Ah[mt][ks][1] = lds32(a + 8 * RS);
            Ah[mt][ks][2] = lds32(a + 16);
            Ah[mt][ks][3] = lds32(a + 8 * RS + 16);
        }
    float znr[4];
    #pragma unroll
    for (int j = 0; j < 4; j++) znr[j] = zn_s[Rb + j * 8];
    __syncthreads();

    issue_chunk(sb, tid, 0, 0);
    asm volatile("cp.async.commit_group;" ::: "memory");
    issue_chunk(sb, tid, 1, 1);
    asm volatile("cp.async.commit_group;" ::: "memory");
    issue_chunk(sb, tid, 2, 2);
    asm volatile("cp.async.commit_group;" ::: "memory");

    float acc[2][8][4];
    #pragma unroll
    for (int mt = 0; mt < 2; mt++)
        #pragma unroll
        for (int nt = 0; nt < 8; nt++)
            #pragma unroll
            for (int q = 0; q < 4; q++) acc[mt][nt][q] = 0.0f;

    float v1[4], v2[4], v3[4], v4[4];
    int   i1[4], i2[4], i3[4];
    #pragma unroll
    for (int j = 0; j < 4; j++) {
        v1[j] = CUDART_INF_F; v2[j] = CUDART_INF_F;
        v3[j] = CUDART_INF_F; v4[j] = CUDART_INF_F;
        i1[j] = 0; i2[j] = 0; i3[j] = 0;
    }

    const unsigned bfrag_base = sb + OFF_BST + (lane >> 2) * RS + Cb * 2;
    const float DS = -3.0517578125e-05f;   // -2 * 2^-16

    #define UPD4(sl, dv, cd) \
        if ((dv) < v1[sl]) { v4[sl]=v3[sl]; v3[sl]=v2[sl]; i3[sl]=i2[sl]; \
                             v2[sl]=v1[sl]; i2[sl]=i1[sl]; v1[sl]=(dv); i1[sl]=(cd); } \
        else if ((dv) < v2[sl]) { v4[sl]=v3[sl]; v3[sl]=v2[sl]; i3[sl]=i2[sl]; \
                                  v2[sl]=(dv); i2[sl]=(cd); } \
        else if ((dv) < v3[sl]) { v4[sl]=v3[sl]; v3[sl]=(dv); i3[sl]=(cd); } \
        else if ((dv) < v4[sl]) v4[sl]=(dv);

    for (int cn = 0; cn < N_CHUNKS; cn++) {
        asm volatile("cp.async.wait_group 2;" ::: "memory");
        __syncthreads();
        const unsigned sbase = (unsigned)(cn % NSTAGE) * STAGE_B;

        #pragma unroll
        for (int ks = 0; ks < 8; ks++) {
            #pragma unroll
            for (int nt = 0; nt < 8; nt++) {
                unsigned ba = bfrag_base + sbase + nt * 8 * RS + ks * 32;
                unsigned b0 = lds32(ba), b1 = lds32(ba + 16);
                mma_f16(acc[0][nt], Ah[0][ks], b0, b1);
                mma_f16(acc[1][nt], Ah[1][ks], b0, b1);
            }
        }
        __syncthreads();
        if (cn + NSTAGE < N_CHUNKS) issue_chunk(sb, tid, cn + NSTAGE, cn % NSTAGE);
        asm volatile("cp.async.commit_group;" ::: "memory");

        #pragma unroll
        for (int nt = 0; nt < 8; nt++) {
            const int code0 = cn * CPC + nt * 8 + (int)Cb;
            float2 e = lds64f(sb + OFF_EN + (unsigned)code0 * 4);
            #pragma unroll
            for (int mt = 0; mt < 2; mt++) {
                float d0 = fmaf(DS, acc[mt][nt][0], znr[2 * mt] + e.x);
                float d1 = fmaf(DS, acc[mt][nt][1], znr[2 * mt] + e.y);
                float d2 = fmaf(DS, acc[mt][nt][2], znr[2 * mt + 1] + e.x);
                float d3 = fmaf(DS, acc[mt][nt][3], znr[2 * mt + 1] + e.y);
                UPD4(2 * mt,     d0, code0);
                UPD4(2 * mt,     d1, code0 + 1);
                UPD4(2 * mt + 1, d2, code0);
                UPD4(2 * mt + 1, d3, code0 + 1);
                acc[mt][nt][0] = 0.0f; acc[mt][nt][1] = 0.0f;
                acc[mt][nt][2] = 0.0f; acc[mt][nt][3] = 0.0f;
            }
        }
    }
    #undef UPD4

    // quad merge of top-4 (values) / top-3 (indices); classify
    #pragma unroll
    for (int j = 0; j < 4; j++) {
        float a1 = v1[j], a2 = v2[j], a3 = v3[j], a4 = v4[j];
        int   b1 = i1[j], b2 = i2[j], b3 = i3[j];

        #define INS(ov, op) \
            if ((ov) < a1 || ((ov) == a1 && (op) < b1)) { \
                a4=a3; a3=a2; b3=b2; a2=a1; b2=b1; a1=(ov); b1=(op); } \
            else if ((ov) < a2 || ((ov) == a2 && (op) < b2)) { \
                a4=a3; a3=a2; b3=b2; a2=(ov); b2=(op); } \
            else if ((ov) < a3 || ((ov) == a3 && (op) < b3)) { \
                a4=a3; a3=(ov); b3=(op); } \
            else if ((ov) < a4) a4=(ov);

        #pragma unroll
        for (int off = 1; off <= 2; off <<= 1) {
            float o1 = __shfl_xor_sync(~0u, a1, off);
            float o2 = __shfl_xor_sync(~0u, a2, off);
            float o3 = __shfl_xor_sync(~0u, a3, off);
            float o4 = __shfl_xor_sync(~0u, a4, off);
            int   p1 = __shfl_xor_sync(~0u, b1, off);
            int   p2 = __shfl_xor_sync(~0u, b2, off);
            int   p3 = __shfl_xor_sync(~0u, b3, off);
            INS(o1, p1);
            INS(o2, p2);
            INS(o3, p3);
            a4 = fminf(a4, o4);   // a lane's 4th-best can never rank top-3 in the union
        }
        #undef INS

        if ((lane & 3) == 0) {
            int token = n0 + (int)Rb + j * 8;
            g_inds[token] = b1;
            float T = 1.0e-3f * sqrtf(znr[j] * enmax) + 6.0e-5f;
            if (a2 - a1 < T) {
                if (a4 - a1 >= T) {
                    int p = atomicAdd(&g_nA, 1);
                    g_listA[p] = token;
                    g_i2a[p] = b2;
                    g_i3a[p] = (a3 - a1 < T) ? b3 : -1;
                } else {
                    int p = atomicAdd(&g_nB, 1);
                    g_listB[p] = token;
                }
            }
        }
    }
}

// ---------- cand: exact R1-numerics compare among <=3 candidate codes ----------
__global__ void __launch_bounds__(256, 1)
vq_cand(const float* __restrict__ batch, const float* __restrict__ w) {
    const int nA = *(volatile int*)&g_nA;
    for (int k = blockIdx.x * 256 + threadIdx.x; k < nA; k += gridDim.x * 256) {
        int token = g_listA[k];
        int ia = g_inds[token], ib = g_i2a[k], ic = g_i3a[k];
        if (ic < 0) ic = ib;    // duplicate -> harmless no-op in tie-break
        const float* zp = batch + (size_t)(token >> 12) * (DIM * 4096) + (token & 4095);
        const float* wa = w + (size_t)ia * DIM;
        const float* wb = w + (size_t)ib * DIM;
        const float* wc = w + (size_t)ic * DIM;
        float zn = 0.0f;
        float loa = 0.0f, hia = 0.0f, lob = 0.0f, hib = 0.0f, loc = 0.0f, hic = 0.0f;
        #pragma unroll 4
        for (int c = 0; c < DIM; c += 2) {
            float z0 = zp[(size_t)c * 4096];
            float z1 = zp[(size_t)(c + 1) * 4096];
            zn = __fadd_rn(zn, __fmul_rn(z0, z0));
            zn = __fadd_rn(zn, __fmul_rn(z1, z1));
            loa = fmaf(z0, wa[c], loa);     hia = fmaf(z1, wa[c + 1], hia);
            lob = fmaf(z0, wb[c], lob);     hib = fmaf(z1, wb[c + 1], hib);
            loc = fmaf(z0, wc[c], loc);     hic = fmaf(z1, wc[c + 1], hic);
        }
        float da = fmaf(-2.0f, __fadd_rn(loa, hia), __fadd_rn(zn, g_enorm[ia]));
        float db = fmaf(-2.0f, __fadd_rn(lob, hib), __fadd_rn(zn, g_enorm[ib]));
        float dc = fmaf(-2.0f, __fadd_rn(loc, hic), __fadd_rn(zn, g_enorm[ic]));
        float bv = da; int bi = ia;
        if (db < bv || (db == bv && ib < bi)) { bv = db; bi = ib; }
        if (dc < bv || (dc == bv && ic < bi)) { bv = dc; bi = ic; }
        g_inds[token] = bi;
    }
}

// ---------- fullB: warp-per-token exact R1-numerics full scan ----------
__global__ void __launch_bounds__(256, 1)
vq_fullB(const float* __restrict__ batch, const float* __restrict__ w) {
    const int nB = *(volatile int*)&g_nB;
    __shared__ float zsm[8][128];

    const int tid = threadIdx.x, wid = tid >> 5, lane = tid & 31;

    for (int k = blockIdx.x * 8 + wid; k < nB; k += gridDim.x * 8) {
        int token = g_listB[k];
        const float* zp = batch + (size_t)(token >> 12) * (DIM * 4096) + (token & 4095);
        #pragma unroll
        for (int c = lane; c < DIM; c += 32)
            zsm[wid][c] = zp[(size_t)c * 4096];
        __syncwarp();

        // znorm: R1 sequential chain (redundant per lane; identical result)
        float zn = 0.0f;
        #pragma unroll 8
        for (int c = 0; c < DIM; c++)
            zn = __fadd_rn(zn, __fmul_rn(zsm[wid][c], zsm[wid][c]));

        float bv = CUDART_INF_F;
        int   bi = 0;
        for (int kk = 0; kk < NUM_CODES / 32; kk++) {
            int code = lane + kk * 32;
            const float* wr = w + (size_t)code * DIM;
            float lo = 0.0f, hi = 0.0f;
            #pragma unroll 8
            for (int c = 0; c < DIM; c += 4) {   // R1 ffma2 order: even chain, odd chain
                lo = fmaf(zsm[wid][c],     __ldg(&wr[c]),     lo);
                hi = fmaf(zsm[wid][c + 1], __ldg(&wr[c + 1]), hi);
                lo = fmaf(zsm[wid][c + 2], __ldg(&wr[c + 2]), lo);
                hi = fmaf(zsm[wid][c + 3], __ldg(&wr[c + 3]), hi);
            }
            float dis = fmaf(-2.0f, __fadd_rn(lo, hi), __fadd_rn(zn, __ldg(&g_enorm[code])));
            if (dis < bv) { bv = dis; bi = code; }   // per-lane codes ascending
        }
        #pragma unroll
        for (int off = 16; off > 0; off >>= 1) {
            float ov = __shfl_xor_sync(~0u, bv, off);
            int   oi = __shfl_xor_sync(~0u, bi, off);
            if (ov < bv || (ov == bv && oi < bi)) { bv = ov; bi = oi; }
        }
        if (lane == 0) g_inds[token] = bi;
        __syncwarp();
    }
}

// ---------- output + loss ----------
__global__ void __launch_bounds__(256, 1)
vq_output(const float* __restrict__ batch, const float* __restrict__ w,
          float* __restrict__ out) {
    __shared__ float qsT[128 * 66];
    __shared__ int   si[64];
    __shared__ float red[512];

    const int tid = threadIdx.x, wid = tid >> 5, lane = tid & 31;
    const int n0 = blockIdx.x * 64, b = n0 >> 12, hw0 = n0 & 4095;

    if (tid < 64) si[tid] = g_inds[n0 + tid];
    __syncthreads();

    const float4* w4 = (const float4*)w;
    #pragma unroll
    for (int k = 0; k < 8; k++) {
        int f = tid + k * 256;
        int r = f >> 5, c4 = f & 31;
        float4 v = __ldg(&w4[(size_t)si[r] * 32 + c4]);
        int cb = c4 * 4;
        qsT[(cb + 0) * 66 + r] = v.x;
        qsT[(cb + 1) * 66 + r] = v.y;
        qsT[(cb + 2) * 66 + r] = v.z;
        qsT[(cb + 3) * 66 + r] = v.w;
    }
    __syncthreads();

    float s1 = 0.0f, s3 = 0.0f;
    #pragma unroll 4
    for (int it = 0; it < 16; it++) {
        int c = wid * 16 + it;
        size_t go = ((size_t)(b * 128 + c)) * 4096 + hw0 + 2 * lane;
        float2 z2 = *(const float2*)(batch + go);
        float q0 = qsT[c * 66 + 2 * lane];
        float q1 = qsT[c * 66 + 2 * lane + 1];
        float dq0 = q0 - z2.x, dq1 = q1 - z2.y;
        float ov0 = z2.x + dq0, ov1 = z2.y + dq1;
        float d30 = z2.x - ov0, d31 = z2.y - ov1;
        *(float2*)(out + go) = make_float2(ov0, ov1);
        s1 += dq0 * dq0 + dq1 * dq1;
        s3 += d30 * d30 + d31 * d31;
    }
    red[tid] = s1; red[256 + tid] = s3;
    __syncthreads();
    #pragma unroll
    for (int st = 128; st > 0; st >>= 1) {
        if (tid < st) { red[tid] += red[tid + st]; red[256 + tid] += red[256 + tid + st]; }
        __syncthreads();
    }
    if (tid == 0) {
        atomicAdd(&g_s1, (double)red[0]);
        atomicAdd(&g_s3, (double)red[256]);
    }
}

// ---------- finalize ----------
__global__ void vq_finalize(float* __restrict__ out, int out_size) {
    if (out_size <= TOT_ELEMS) return;
    const double inv = 1.0 / (double)TOT_ELEMS;
    float t1 = (float)(g_s1 * inv);
    float t3 = (float)(g_s3 * inv);
    out[TOT_ELEMS] = (t1 + t1) + t3 * 50.0f;
}

// ---------- launch ----------
extern "C" void kernel_launch(void* const* d_in, const int* in_sizes, int n_in,
                              void* d_out, int out_size) {
    const float* batch = (const float*)d_in[0];
    const float* wq    = (const float*)d_in[1];
    if (n_in >= 2 && in_sizes[0] == NUM_CODES * DIM) {
        const float* t = batch; batch = wq; wq = t;
    }
    float* out = (float*)d_out;

    cudaFuncSetAttribute(vq_tensor, cudaFuncAttributeMaxDynamicSharedMemorySize,
                         SMEM_TENSOR);

    vq_prep<<<320, 256>>>(wq);
    vq_tensor<<<N_TOKENS / TPC, 256, SMEM_TENSOR>>>(batch);
    vq_cand<<<64, 256>>>(batch, wq);
    vq_fullB<<<128, 256>>>(batch, wq);
    vq_output<<<N_TOKENS / 64, 256>>>(batch, wq, out);
    vq_finalize<<<1, 1>>>(out, out_size);
}

// round 10
// speedup vs baseline: 1.0660x; 1.0660x over previous
#include <cuda_runtime.h>
#include <cuda_fp16.h>
#include <math_constants.h>

#define NUM_CODES 2560
#define DIM       128
#define N_TOKENS  65536
#define TOT_ELEMS 8388608
#define TPC       256
#define CPC       64
#define N_CHUNKS  40
#define NSTAGE    3

#define RS          272
#define STAGE_B     (64 * RS)
#define OFF_BST     0
#define OFF_EN      69632                  // 256*RS (A temp) dominates 3*STAGE_B
#define OFF_ZN      (OFF_EN + NUM_CODES * 4)
#define SMEM_TENSOR (OFF_ZN + 1024)

__device__ __align__(16) float  g_enorm[NUM_CODES];
__device__ __align__(16) __half g_wh16[NUM_CODES * DIM];   // fp16(w * 4096)
__device__ int    g_enmax_i = 0;
__device__ int    g_inds[N_TOKENS];
__device__ int    g_listA[N_TOKENS];
__device__ int    g_i2a[N_TOKENS];
__device__ int    g_listB[N_TOKENS];
__device__ int    g_nA, g_nB;
__device__ double g_s1, g_s3;

// ---------- helpers ----------
__device__ __forceinline__ unsigned smem_u32(const void* p) {
    unsigned a;
    asm("{ .reg .u64 t; cvta.to.shared.u64 t, %1; cvt.u32.u64 %0, t; }" : "=r"(a) : "l"(p));
    return a;
}
__device__ __forceinline__ unsigned lds32(unsigned a) {
    unsigned v;
    asm volatile("ld.shared.b32 %0, [%1];" : "=r"(v) : "r"(a));
    return v;
}
__device__ __forceinline__ float2 lds64f(unsigned a) {
    float2 v;
    asm volatile("ld.shared.v2.f32 {%0, %1}, [%2];" : "=f"(v.x), "=f"(v.y) : "r"(a));
    return v;
}
__device__ __forceinline__ void mma_f16(float* c, const unsigned* a,
                                        unsigned b0, unsigned b1) {
    asm volatile(
        "mma.sync.aligned.m16n8k16.row.col.f32.f16.f16.f32 "
        "{%0,%1,%2,%3}, {%4,%5,%6,%7}, {%8,%9}, {%0,%1,%2,%3};"
        : "+f"(c[0]), "+f"(c[1]), "+f"(c[2]), "+f"(c[3])
        : "r"(a[0]), "r"(a[1]), "r"(a[2]), "r"(a[3]), "r"(b0), "r"(b1));
}

// ---------- prep: enorm (+max) + fp16(w*4096) ----------
__global__ void vq_prep(const float* __restrict__ w) {
    int gtid = blockIdx.x * blockDim.x + threadIdx.x;
    if (gtid == 0) { g_s1 = 0.0; g_s3 = 0.0; g_nA = 0; g_nB = 0; }
    int gw = gtid >> 5, lane = threadIdx.x & 31;
    if (gw < NUM_CODES) {
        const float* row = w + (size_t)gw * DIM;
        float s = 0.0f;
        #pragma unroll
        for (int k = lane; k < DIM; k += 32) {
            float v = row[k];
            s = __fadd_rn(s, __fmul_rn(v, v));
        }
        #pragma unroll
        for (int off = 16; off > 0; off >>= 1) s += __shfl_xor_sync(~0u, s, off);
        if (lane == 0) {
            g_enorm[gw] = s;
            atomicMax(&g_enmax_i, __float_as_int(s));
        }
    }
    int stride = gridDim.x * blockDim.x;
    for (int i = gtid; i < NUM_CODES * DIM; i += stride)
        g_wh16[i] = __float2half_rn(w[i] * 4096.0f);
}

// ---------- tensor pass (R8 structure: top-3 values, 2 indices) ----------
__device__ __forceinline__ void issue_chunk(unsigned sb, int tid, int cn, int st) {
    const uint4* gh = ((const uint4*)g_wh16) + (size_t)cn * 1024;
    unsigned base = sb + OFF_BST + st * STAGE_B;
    #pragma unroll
    for (int i = 0; i < 4; i++) {
        int f = tid + i * 256;
        unsigned d = base + (f >> 4) * RS + (f & 15) * 16;
        asm volatile("cp.async.cg.shared.global [%0], [%1], 16;" :: "r"(d), "l"(gh + f));
    }
}

__global__ void __launch_bounds__(256, 1)
vq_tensor(const float* __restrict__ batch) {
    extern __shared__ char smem[];
    const unsigned sb = smem_u32(smem);
    float* zn_s = (float*)(smem + OFF_ZN);

    const int tid = threadIdx.x, wid = tid >> 5, lane = tid & 31;
    const int n0 = blockIdx.x * TPC, b = n0 >> 12, hw0 = n0 & 4095;
    const float* zbase = batch + (size_t)b * (DIM * 4096) + hw0;
    const float enmax = __int_as_float(g_enmax_i);

    {
        const float* zp = zbase + tid;
        float acc = 0.0f;
        #pragma unroll 4
        for (int c = 0; c < DIM; c += 2) {
            float z0 = zp[(size_t)c * 4096];
            float z1 = zp[(size_t)(c + 1) * 4096];
            acc = __fadd_rn(acc, __fmul_rn(z0, z0));
            acc = __fadd_rn(acc, __fmul_rn(z1, z1));
            __half h0 = __float2half_rn(z0 * 16.0f);
            __half h1 = __float2half_rn(z1 * 16.0f);
            unsigned hp = (unsigned)__half_as_ushort(h0) |
                          ((unsigned)__half_as_ushort(h1) << 16);
            *(unsigned*)(smem + OFF_BST + tid * RS + c * 2) = hp;
        }
        zn_s[tid] = acc;
    }
    for (int i = tid; i < NUM_CODES; i += 256)
        ((float*)(smem + OFF_EN))[i] = g_enorm[i];
    __syncthreads();

    const unsigned Rb = wid * 32 + (lane >> 2);
    const unsigned Cb = (lane & 3) * 2;
    unsigned Ah[2][8][4];
    #pragma unroll
    for (int mt = 0; mt < 2; mt++)
        #pragma unroll
        for (int ks = 0; ks < 8; ks++) {
            unsigned a = sb + OFF_BST + (Rb + mt * 16) * RS + (ks * 16 + Cb) * 2;
            Ah[mt][ks][0] = lds32(a);
            Ah[mt][ks][1] = lds32(a + 8 * RS);
            Ah[mt][ks][2] = lds32(a + 16);
            Ah[mt][ks][3] = lds32(a + 8 * RS + 16);
        }
    float znr[4];
    #pragma unroll
    for (int j = 0; j < 4; j++) znr[j] = zn_s[Rb + j * 8];
    __syncthreads();

    issue_chunk(sb, tid, 0, 0);
    asm volatile("cp.async.commit_group;" ::: "memory");
    issue_chunk(sb, tid, 1, 1);
    asm volatile("cp.async.commit_group;" ::: "memory");
    issue_chunk(sb, tid, 2, 2);
    asm volatile("cp.async.commit_group;" ::: "memory");

    float acc[2][8][4];
    #pragma unroll
    for (int mt = 0; mt < 2; mt++)
        #pragma unroll
        for (int nt = 0; nt < 8; nt++)
            #pragma unroll
            for (int q = 0; q < 4; q++) acc[mt][nt][q] = 0.0f;

    float v1[4], v2[4], v3[4];
    int   i1[4], i2[4];
    #pragma unroll
    for (int j = 0; j < 4; j++) {
        v1[j] = CUDART_INF_F; v2[j] = CUDART_INF_F; v3[j] = CUDART_INF_F;
        i1[j] = 0; i2[j] = 0;
    }

    const unsigned bfrag_base = sb + OFF_BST + (lane >> 2) * RS + Cb * 2;
    const float DS = -3.0517578125e-05f;   // -2 * 2^-16

    #define UPD(sl, dv, cd) \
        if ((dv) < v1[sl]) { v3[sl]=v2[sl]; v2[sl]=v1[sl]; i2[sl]=i1[sl]; v1[sl]=(dv); i1[sl]=(cd); } \
        else if ((dv) < v2[sl]) { v3[sl]=v2[sl]; v2[sl]=(dv); i2[sl]=(cd); } \
        else if ((dv) < v3[sl]) v3[sl]=(dv);

    for (int cn = 0; cn < N_CHUNKS; cn++) {
        asm volatile("cp.async.wait_group 2;" ::: "memory");
        __syncthreads();
        const unsigned sbase = (unsigned)(cn % NSTAGE) * STAGE_B;

        #pragma unroll
        for (int ks = 0; ks < 8; ks++) {
            #pragma unroll
            for (int nt = 0; nt < 8; nt++) {
                unsigned ba = bfrag_base + sbase + nt * 8 * RS + ks * 32;
                unsigned b0 = lds32(ba), b1 = lds32(ba + 16);
                mma_f16(acc[0][nt], Ah[0][ks], b0, b1);
                mma_f16(acc[1][nt], Ah[1][ks], b0, b1);
            }
        }
        __syncthreads();
        if (cn + NSTAGE < N_CHUNKS) issue_chunk(sb, tid, cn + NSTAGE, cn % NSTAGE);
        asm volatile("cp.async.commit_group;" ::: "memory");

        #pragma unroll
        for (int nt = 0; nt < 8; nt++) {
            const int code0 = cn * CPC + nt * 8 + (int)Cb;
            float2 e = lds64f(sb + OFF_EN + (unsigned)code0 * 4);
            #pragma unroll
            for (int mt = 0; mt < 2; mt++) {
                float d0 = fmaf(DS, acc[mt][nt][0], znr[2 * mt] + e.x);
                float d1 = fmaf(DS, acc[mt][nt][1], znr[2 * mt] + e.y);
                float d2 = fmaf(DS, acc[mt][nt][2], znr[2 * mt + 1] + e.x);
                float d3 = fmaf(DS, acc[mt][nt][3], znr[2 * mt + 1] + e.y);
                UPD(2 * mt,     d0, code0);
                UPD(2 * mt,     d1, code0 + 1);
                UPD(2 * mt + 1, d2, code0);
                UPD(2 * mt + 1, d3, code0 + 1);
                acc[mt][nt][0] = 0.0f; acc[mt][nt][1] = 0.0f;
                acc[mt][nt][2] = 0.0f; acc[mt][nt][3] = 0.0f;
            }
        }
    }
    #undef UPD

    // quad merge of top-3 + classify
    #pragma unroll
    for (int j = 0; j < 4; j++) {
        float a1 = v1[j], a2 = v2[j], a3 = v3[j];
        int   b1 = i1[j], b2 = i2[j];
        #pragma unroll
        for (int off = 1; off <= 2; off <<= 1) {
            float o1 = __shfl_xor_sync(~0u, a1, off);
            int   p1 = __shfl_xor_sync(~0u, b1, off);
            float o2 = __shfl_xor_sync(~0u, a2, off);
            int   p2 = __shfl_xor_sync(~0u, b2, off);
            float o3 = __shfl_xor_sync(~0u, a3, off);
            if (o1 < a1 || (o1 == a1 && p1 < b1)) {
                a3 = a2; a2 = a1; b2 = b1; a1 = o1; b1 = p1;
            } else if (o1 < a2 || (o1 == a2 && p1 < b2)) {
                a3 = a2; a2 = o1; b2 = p1;
            } else if (o1 < a3) a3 = o1;
            if (o2 < a2 || (o2 == a2 && p2 < b2)) {
                a3 = a2; a2 = o2; b2 = p2;
            } else if (o2 < a3) a3 = o2;
            if (o3 < a3) a3 = o3;
        }
        if ((lane & 3) == 0) {
            int token = n0 + (int)Rb + j * 8;
            g_inds[token] = b1;
            float T = 1.0e-3f * sqrtf(znr[j] * enmax) + 6.0e-5f;
            if (a2 - a1 < T) {
                if (a3 - a1 >= T) {
                    int p = atomicAdd(&g_nA, 1);
                    g_listA[p] = token; g_i2a[p] = b2;
                } else {
                    int p = atomicAdd(&g_nB, 1);
                    g_listB[p] = token;
                }
            }
        }
    }
}

// ---------- pairA: exact R1-numerics compare of the two candidate codes ----------
__global__ void __launch_bounds__(256, 1)
vq_pairA(const float* __restrict__ batch, const float* __restrict__ w) {
    const int nA = *(volatile int*)&g_nA;
    for (int k = blockIdx.x * 256 + threadIdx.x; k < nA; k += gridDim.x * 256) {
        int token = g_listA[k];
        int ia = g_inds[token], ib = g_i2a[k];
        const float* zp = batch + (size_t)(token >> 12) * (DIM * 4096) + (token & 4095);
        const float* wa = w + (size_t)ia * DIM;
        const float* wb = w + (size_t)ib * DIM;
        float zn = 0.0f, loa = 0.0f, hia = 0.0f, lob = 0.0f, hib = 0.0f;
        #pragma unroll 4
        for (int c = 0; c < DIM; c += 2) {
            float z0 = zp[(size_t)c * 4096];
            float z1 = zp[(size_t)(c + 1) * 4096];
            zn = __fadd_rn(zn, __fmul_rn(z0, z0));
            zn = __fadd_rn(zn, __fmul_rn(z1, z1));
            loa = fmaf(z0, wa[c], loa);     hia = fmaf(z1, wa[c + 1], hia);
            lob = fmaf(z0, wb[c], lob);     hib = fmaf(z1, wb[c + 1], hib);
        }
        float da = fmaf(-2.0f, __fadd_rn(loa, hia), __fadd_rn(zn, g_enorm[ia]));
        float db = fmaf(-2.0f, __fadd_rn(lob, hib), __fadd_rn(zn, g_enorm[ib]));
        if (db < da || (db == da && ib < ia)) g_inds[token] = ib;
    }
}

// ---------- fullB: warp-per-token exact R1-numerics full scan (R9, measured 1.3us) ----------
__global__ void __launch_bounds__(256, 1)
vq_fullB(const float* __restrict__ batch, const float* __restrict__ w) {
    const int nB = *(volatile int*)&g_nB;
    __shared__ float zsm[8][128];

    const int tid = threadIdx.x, wid = tid >> 5, lane = tid & 31;

    for (int k = blockIdx.x * 8 + wid; k < nB; k += gridDim.x * 8) {
        int token = g_listB[k];
        const float* zp = batch + (size_t)(token >> 12) * (DIM * 4096) + (token & 4095);
        #pragma unroll
        for (int c = lane; c < DIM; c += 32)
            zsm[wid][c] = zp[(size_t)c * 4096];
        __syncwarp();

        float zn = 0.0f;
        #pragma unroll 8
        for (int c = 0; c < DIM; c++)
            zn = __fadd_rn(zn, __fmul_rn(zsm[wid][c], zsm[wid][c]));

        float bv = CUDART_INF_F;
        int   bi = 0;
        for (int kk = 0; kk < NUM_CODES / 32; kk++) {
            int code = lane + kk * 32;
            const float* wr = w + (size_t)code * DIM;
            float lo = 0.0f, hi = 0.0f;
            #pragma unroll 8
            for (int c = 0; c < DIM; c += 4) {
                lo = fmaf(zsm[wid][c],     __ldg(&wr[c]),     lo);
                hi = fmaf(zsm[wid][c + 1], __ldg(&wr[c + 1]), hi);
                lo = fmaf(zsm[wid][c + 2], __ldg(&wr[c + 2]), lo);
                hi = fmaf(zsm[wid][c + 3], __ldg(&wr[c + 3]), hi);
            }
            float dis = fmaf(-2.0f, __fadd_rn(lo, hi), __fadd_rn(zn, __ldg(&g_enorm[code])));
            if (dis < bv) { bv = dis; bi = code; }
        }
        #pragma unroll
        for (int off = 16; off > 0; off >>= 1) {
            float ov = __shfl_xor_sync(~0u, bv, off);
            int   oi = __shfl_xor_sync(~0u, bi, off);
            if (ov < bv || (ov == bv && oi < bi)) { bv = ov; bi = oi; }
        }
        if (lane == 0) g_inds[token] = bi;
        __syncwarp();
    }
}

// ---------- output + loss ----------
__global__ void __launch_bounds__(256, 1)
vq_output(const float* __restrict__ batch, const float* __restrict__ w,
          float* __restrict__ out) {
    __shared__ float qsT[128 * 66];
    __shared__ int   si[64];
    __shared__ float red[512];

    const int tid = threadIdx.x, wid = tid >> 5, lane = tid & 31;
    const int n0 = blockIdx.x * 64, b = n0 >> 12, hw0 = n0 & 4095;

    if (tid < 64) si[tid] = g_inds[n0 + tid];
    __syncthreads();

    const float4* w4 = (const float4*)w;
    #pragma unroll
    for (int k = 0; k < 8; k++) {
        int f = tid + k * 256;
        int r = f >> 5, c4 = f & 31;
        float4 v = __ldg(&w4[(size_t)si[r] * 32 + c4]);
        int cb = c4 * 4;
        qsT[(cb + 0) * 66 + r] = v.x;
        qsT[(cb + 1) * 66 + r] = v.y;
        qsT[(cb + 2) * 66 + r] = v.z;
        qsT[(cb + 3) * 66 + r] = v.w;
    }
    __syncthreads();

    float s1 = 0.0f, s3 = 0.0f;
    #pragma unroll 4
    for (int it = 0; it < 16; it++) {
        int c = wid * 16 + it;
        size_t go = ((size_t)(b * 128 + c)) * 4096 + hw0 + 2 * lane;
        float2 z2 = *(const float2*)(batch + go);
        float q0 = qsT[c * 66 + 2 * lane];
        float q1 = qsT[c * 66 + 2 * lane + 1];
        float dq0 = q0 - z2.x, dq1 = q1 - z2.y;
        float ov0 = z2.x + dq0, ov1 = z2.y + dq1;
        float d30 = z2.x - ov0, d31 = z2.y - ov1;
        *(float2*)(out + go) = make_float2(ov0, ov1);
        s1 += dq0 * dq0 + dq1 * dq1;
        s3 += d30 * d30 + d31 * d31;
    }
    red[tid] = s1; red[256 + tid] = s3;
    __syncthreads();
    #pragma unroll
    for (int st = 128; st > 0; st >>= 1) {
        if (tid < st) { red[tid] += red[tid + st]; red[256 + tid] += red[256 + tid + st]; }
        __syncthreads();
    }
    if (tid == 0) {
        atomicAdd(&g_s1, (double)red[0]);
        atomicAdd(&g_s3, (double)red[256]);
    }
}

// ---------- finalize ----------
__global__ void vq_finalize(float* __restrict__ out, int out_size) {
    if (out_size <= TOT_ELEMS) return;
    const double inv = 1.0 / (double)TOT_ELEMS;
    float t1 = (float)(g_s1 * inv);
    float t3 = (float)(g_s3 * inv);
    out[TOT_ELEMS] = (t1 + t1) + t3 * 50.0f;
}

// ---------- launch ----------
extern "C" void kernel_launch(void* const* d_in, const int* in_sizes, int n_in,
                              void* d_out, int out_size) {
    const float* batch = (const float*)d_in[0];
    const float* wq    = (const float*)d_in[1];
    if (n_in >= 2 && in_sizes[0] == NUM_CODES * DIM) {
        const float* t = batch; batch = wq; wq = t;
    }
    float* out = (float*)d_out;

    cudaFuncSetAttribute(vq_tensor, cudaFuncAttributeMaxDynamicSharedMemorySize,
                         SMEM_TENSOR);

    vq_prep<<<320, 256>>>(wq);
    vq_tensor<<<N_TOKENS / TPC, 256, SMEM_TENSOR>>>(batch);
    vq_pairA<<<64, 256>>>(batch, wq);
    vq_fullB<<<128, 256>>>(batch, wq);
    vq_output<<<N_TOKENS / 64, 256>>>(batch, wq, out);
    vq_finalize<<<1, 1>>>(out, out_size);
}

// round 11
// speedup vs baseline: 3.4809x; 3.2655x over previous
#include <cuda_runtime.h>
#include <cuda_fp16.h>
#include <math_constants.h>

#define NUM_CODES 2560
#define DIM       128
#define N_TOKENS  65536
#define TOT_ELEMS 8388608
#define TPC       256
#define CPC       64
#define N_CHUNKS  40
#define NSTAGE    3

#define RS          272
#define STAGE_B     (64 * RS)
#define OFF_BST     0
#define OFF_EN      69632                  // 256*RS (A temp) dominates 3*STAGE_B
#define OFF_ZN      (OFF_EN + NUM_CODES * 4)
#define SMEM_TENSOR (OFF_ZN + 1024)

// recheck (R1-core) smem layout, in floats
#define ZSTR        132
#define RT          16
#define R_CHUNK     256
#define R_NCH       10

__device__ __align__(16) float  g_enorm[NUM_CODES];
__device__ __align__(16) __half g_wh16[NUM_CODES * DIM];   // fp16(w * 4096)
__device__ int    g_enmax_i = 0;
__device__ int    g_inds[N_TOKENS];
__device__ int    g_listA[N_TOKENS];
__device__ int    g_i2a[N_TOKENS];
__device__ int    g_listB[N_TOKENS];
__device__ int    g_nA, g_nB;
__device__ double g_s1, g_s3;

// ---------- helpers ----------
__device__ __forceinline__ unsigned smem_u32(const void* p) {
    unsigned a;
    asm("{ .reg .u64 t; cvta.to.shared.u64 t, %1; cvt.u32.u64 %0, t; }" : "=r"(a) : "l"(p));
    return a;
}
__device__ __forceinline__ unsigned lds32(unsigned a) {
    unsigned v;
    asm volatile("ld.shared.b32 %0, [%1];" : "=r"(v) : "r"(a));
    return v;
}
__device__ __forceinline__ float2 lds64f(unsigned a) {
    float2 v;
    asm volatile("ld.shared.v2.f32 {%0, %1}, [%2];" : "=f"(v.x), "=f"(v.y) : "r"(a));
    return v;
}
__device__ __forceinline__ void mma_f16(float* c, const unsigned* a,
                                        unsigned b0, unsigned b1) {
    asm volatile(
        "mma.sync.aligned.m16n8k16.row.col.f32.f16.f16.f32 "
        "{%0,%1,%2,%3}, {%4,%5,%6,%7}, {%8,%9}, {%0,%1,%2,%3};"
        : "+f"(c[0]), "+f"(c[1]), "+f"(c[2]), "+f"(c[3])
        : "r"(a[0]), "r"(a[1]), "r"(a[2]), "r"(a[3]), "r"(b0), "r"(b1));
}
__device__ __forceinline__ unsigned long long ffma2(unsigned long long a,
                                                    unsigned long long b,
                                                    unsigned long long c) {
    unsigned long long d;
    asm("fma.rn.f32x2 %0, %1, %2, %3;" : "=l"(d) : "l"(a), "l"(b), "l"(c));
    return d;
}
__device__ __forceinline__ void unpack2(unsigned long long p, float& lo, float& hi) {
    asm("mov.b64 {%0, %1}, %2;" : "=f"(lo), "=f"(hi) : "l"(p));
}

// ---------- prep: enorm (+max) + fp16(w*4096) ----------
__global__ void vq_prep(const float* __restrict__ w) {
    int gtid = blockIdx.x * blockDim.x + threadIdx.x;
    if (gtid == 0) { g_s1 = 0.0; g_s3 = 0.0; g_nA = 0; g_nB = 0; }
    int gw = gtid >> 5, lane = threadIdx.x & 31;
    if (gw < NUM_CODES) {
        const float* row = w + (size_t)gw * DIM;
        float s = 0.0f;
        #pragma unroll
        for (int k = lane; k < DIM; k += 32) {
            float v = row[k];
            s = __fadd_rn(s, __fmul_rn(v, v));
        }
        #pragma unroll
        for (int off = 16; off > 0; off >>= 1) s += __shfl_xor_sync(~0u, s, off);
        if (lane == 0) {
            g_enorm[gw] = s;
            atomicMax(&g_enmax_i, __float_as_int(s));
        }
    }
    int stride = gridDim.x * blockDim.x;
    for (int i = gtid; i < NUM_CODES * DIM; i += stride)
        g_wh16[i] = __float2half_rn(w[i] * 4096.0f);
}

// ---------- tensor pass ----------
__device__ __forceinline__ void issue_chunk(unsigned sb, int tid, int cn, int st) {
    const uint4* gh = ((const uint4*)g_wh16) + (size_t)cn * 1024;
    unsigned base = sb + OFF_BST + st * STAGE_B;
    #pragma unroll
    for (int i = 0; i < 4; i++) {
        int f = tid + i * 256;
        unsigned d = base + (f >> 4) * RS + (f & 15) * 16;
        asm volatile("cp.async.cg.shared.global [%0], [%1], 16;" :: "r"(d), "l"(gh + f));
    }
}

__global__ void __launch_bounds__(256, 1)
vq_tensor(const float* __restrict__ batch) {
    extern __shared__ char smem[];
    const unsigned sb = smem_u32(smem);
    float* zn_s = (float*)(smem + OFF_ZN);

    const int tid = threadIdx.x, wid = tid >> 5, lane = tid & 31;
    const int n0 = blockIdx.x * TPC, b = n0 >> 12, hw0 = n0 & 4095;
    const float* zbase = batch + (size_t)b * (DIM * 4096) + hw0;
    const float enmax = __int_as_float(g_enmax_i);

    {
        const float* zp = zbase + tid;
        float acc = 0.0f;
        #pragma unroll 4
        for (int c = 0; c < DIM; c += 2) {
            float z0 = zp[(size_t)c * 4096];
            float z1 = zp[(size_t)(c + 1) * 4096];
            acc = __fadd_rn(acc, __fmul_rn(z0, z0));
            acc = __fadd_rn(acc, __fmul_rn(z1, z1));
            __half h0 = __float2half_rn(z0 * 16.0f);
            __half h1 = __float2half_rn(z1 * 16.0f);
            unsigned hp = (unsigned)__half_as_ushort(h0) |
                          ((unsigned)__half_as_ushort(h1) << 16);
            *(unsigned*)(smem + OFF_BST + tid * RS + c * 2) = hp;
        }
        zn_s[tid] = acc;
    }
    for (int i = tid; i < NUM_CODES; i += 256)
        ((float*)(smem + OFF_EN))[i] = g_enorm[i];
    __syncthreads();

    const unsigned Rb = wid * 32 + (lane >> 2);
    const unsigned Cb = (lane & 3) * 2;
    unsigned Ah[2][8][4];
    #pragma unroll
    for (int mt = 0; mt < 2; mt++)
        #pragma unroll
        for (int ks = 0; ks < 8; ks++) {
            unsigned a = sb + OFF_BST + (Rb + mt * 16) * RS + (ks * 16 + Cb) * 2;
            Ah[mt][ks][0] = lds32(a);
            Ah[mt][ks][1] = lds32(a + 8 * RS);
            Ah[mt][ks][2] = lds32(a + 16);
            Ah[mt][ks][3] = lds32(a + 8 * RS + 16);
        }
    float znr[4];
    #pragma unroll
    for (int j = 0; j < 4; j++) znr[j] = zn_s[Rb + j * 8];
    __syncthreads();

    issue_chunk(sb, tid, 0, 0);
    asm volatile("cp.async.commit_group;" ::: "memory");
    issue_chunk(sb, tid, 1, 1);
    asm volatile("cp.async.commit_group;" ::: "memory");
    issue_chunk(sb, tid, 2, 2);
    asm volatile("cp.async.commit_group;" ::: "memory");

    float acc[2][8][4];
    #pragma unroll
    for (int mt = 0; mt < 2; mt++)
        #pragma unroll
        for (int nt = 0; nt < 8; nt++)
            #pragma unroll
            for (int q = 0; q < 4; q++) acc[mt][nt][q] = 0.0f;

    float v1[4], v2[4], v3[4];
    int   i1[4], i2[4];
    #pragma unroll
    for (int j = 0; j < 4; j++) {
        v1[j] = CUDART_INF_F; v2[j] = CUDART_INF_F; v3[j] = CUDART_INF_F;
        i1[j] = 0; i2[j] = 0;
    }

    const unsigned bfrag_base = sb + OFF_BST + (lane >> 2) * RS + Cb * 2;
    const float DS = -3.0517578125e-05f;   // -2 * 2^-16

    #define UPD(sl, dv, cd) \
        if ((dv) < v1[sl]) { v3[sl]=v2[sl]; v2[sl]=v1[sl]; i2[sl]=i1[sl]; v1[sl]=(dv); i1[sl]=(cd); } \
        else if ((dv) < v2[sl]) { v3[sl]=v2[sl]; v2[sl]=(dv); i2[sl]=(cd); } \
        else if ((dv) < v3[sl]) v3[sl]=(dv);

    for (int cn = 0; cn < N_CHUNKS; cn++) {
        asm volatile("cp.async.wait_group 2;" ::: "memory");
        __syncthreads();
        const unsigned sbase = (unsigned)(cn % NSTAGE) * STAGE_B;

        #pragma unroll
        for (int ks = 0; ks < 8; ks++) {
            #pragma unroll
            for (int nt = 0; nt < 8; nt++) {
                unsigned ba = bfrag_base + sbase + nt * 8 * RS + ks * 32;
                unsigned b0 = lds32(ba), b1 = lds32(ba + 16);
                mma_f16(acc[0][nt], Ah[0][ks], b0, b1);
                mma_f16(acc[1][nt], Ah[1][ks], b0, b1);
            }
        }
        __syncthreads();
        if (cn + NSTAGE < N_CHUNKS) issue_chunk(sb, tid, cn + NSTAGE, cn % NSTAGE);
        asm volatile("cp.async.commit_group;" ::: "memory");

        // ---- distances in place ----
        #pragma unroll
        for (int nt = 0; nt < 8; nt++) {
            const int code0 = cn * CPC + nt * 8 + (int)Cb;
            float2 e = lds64f(sb + OFF_EN + (unsigned)code0 * 4);
            #pragma unroll
            for (int mt = 0; mt < 2; mt++) {
                acc[mt][nt][0] = fmaf(DS, acc[mt][nt][0], znr[2 * mt] + e.x);
                acc[mt][nt][1] = fmaf(DS, acc[mt][nt][1], znr[2 * mt] + e.y);
                acc[mt][nt][2] = fmaf(DS, acc[mt][nt][2], znr[2 * mt + 1] + e.x);
                acc[mt][nt][3] = fmaf(DS, acc[mt][nt][3], znr[2 * mt + 1] + e.y);
            }
        }
        // ---- per-slot chunk-min; rescan only if it can enter top-3 ----
        #pragma unroll
        for (int mt = 0; mt < 2; mt++) {
            #pragma unroll
            for (int half = 0; half < 2; half++) {
                const int sl = 2 * mt + half;
                float m = fminf(acc[mt][0][2 * half], acc[mt][0][2 * half + 1]);
                #pragma unroll
                for (int nt = 1; nt < 8; nt++)
                    m = fminf(m, fminf(acc[mt][nt][2 * half], acc[mt][nt][2 * half + 1]));
                if (m < v3[sl]) {
                    #pragma unroll
                    for (int nt = 0; nt < 8; nt++) {
                        const int code0 = cn * CPC + nt * 8 + (int)Cb;
                        float dA = acc[mt][nt][2 * half];
                        float dB = acc[mt][nt][2 * half + 1];
                        UPD(sl, dA, code0);
                        UPD(sl, dB, code0 + 1);
                    }
                }
            }
        }
        // ---- reset acc ----
        #pragma unroll
        for (int mt = 0; mt < 2; mt++)
            #pragma unroll
            for (int nt = 0; nt < 8; nt++) {
                acc[mt][nt][0] = 0.0f; acc[mt][nt][1] = 0.0f;
                acc[mt][nt][2] = 0.0f; acc[mt][nt][3] = 0.0f;
            }
    }
    #undef UPD

    // quad merge of top-3 + classify
    #pragma unroll
    for (int j = 0; j < 4; j++) {
        float a1 = v1[j], a2 = v2[j], a3 = v3[j];
        int   b1 = i1[j], b2 = i2[j];
        #pragma unroll
        for (int off = 1; off <= 2; off <<= 1) {
            float o1 = __shfl_xor_sync(~0u, a1, off);
            int   p1 = __shfl_xor_sync(~0u, b1, off);
            float o2 = __shfl_xor_sync(~0u, a2, off);
            int   p2 = __shfl_xor_sync(~0u, b2, off);
            float o3 = __shfl_xor_sync(~0u, a3, off);
            if (o1 < a1 || (o1 == a1 && p1 < b1)) {
                a3 = a2; a2 = a1; b2 = b1; a1 = o1; b1 = p1;
            } else if (o1 < a2 || (o1 == a2 && p1 < b2)) {
                a3 = a2; a2 = o1; b2 = p1;
            } else if (o1 < a3) a3 = o1;
            if (o2 < a2 || (o2 == a2 && p2 < b2)) {
                a3 = a2; a2 = o2; b2 = p2;
            } else if (o2 < a3) a3 = o2;
            if (o3 < a3) a3 = o3;
        }
        if ((lane & 3) == 0) {
            int token = n0 + (int)Rb + j * 8;
            g_inds[token] = b1;
            float T = 1.0e-3f * sqrtf(znr[j] * enmax) + 6.0e-5f;
            if (a2 - a1 < T) {
                if (a3 - a1 >= T) {
                    int p = atomicAdd(&g_nA, 1);
                    g_listA[p] = token; g_i2a[p] = b2;
                } else {
                    int p = atomicAdd(&g_nB, 1);
                    g_listB[p] = token;
                }
            }
        }
    }
}

// ---------- pairA: exact R1-numerics compare of the two candidate codes ----------
__global__ void __launch_bounds__(256, 1)
vq_pairA(const float* __restrict__ batch, const float* __restrict__ w) {
    const int nA = *(volatile int*)&g_nA;
    for (int k = blockIdx.x * 256 + threadIdx.x; k < nA; k += gridDim.x * 256) {
        int token = g_listA[k];
        int ia = g_inds[token], ib = g_i2a[k];
        const float* zp = batch + (size_t)(token >> 12) * (DIM * 4096) + (token & 4095);
        const float* wa = w + (size_t)ia * DIM;
        const float* wb = w + (size_t)ib * DIM;
        float zn = 0.0f, loa = 0.0f, hia = 0.0f, lob = 0.0f, hib = 0.0f;
        #pragma unroll 4
        for (int c = 0; c < DIM; c += 2) {
            float z0 = zp[(size_t)c * 4096];
            float z1 = zp[(size_t)(c + 1) * 4096];
            zn = __fadd_rn(zn, __fmul_rn(z0, z0));
            zn = __fadd_rn(zn, __fmul_rn(z1, z1));
            loa = fmaf(z0, wa[c], loa);     hia = fmaf(z1, wa[c + 1], hia);
            lob = fmaf(z0, wb[c], lob);     hib = fmaf(z1, wb[c + 1], hib);
        }
        float da = fmaf(-2.0f, __fadd_rn(loa, hia), __fadd_rn(zn, g_enorm[ia]));
        float db = fmaf(-2.0f, __fadd_rn(lob, hib), __fadd_rn(zn, g_enorm[ib]));
        if (db < da || (db == da && ib < ia)) g_inds[token] = ib;
    }
}

// ---------- fullB: CTA-based exact R1-numerics full scan (verbatim 507us version) ----------
__global__ void __launch_bounds__(256, 1)
vq_fullB(const float* __restrict__ batch, const float* __restrict__ w) {
    const int base = blockIdx.x * RT;
    const int nf = *(volatile int*)&g_nB;
    if (base >= nf) return;

    extern __shared__ float sm[];
    float* zs = sm;
    float* ws = sm + RT * ZSTR;
    float* zn = ws + R_CHUNK * ZSTR;
    float* en = zn + RT;
    int*   tk = (int*)(en + R_CHUNK);
    int*   tb = tk + RT;
    float* rv = ws;
    int*   ri = (int*)(ws + 512);

    const int tid = threadIdx.x;
    if (tid < RT) {
        int t = (base + tid < nf) ? g_listB[base + tid] : -1;
        tk[tid] = t;
        int tt = (t >= 0) ? t : 0;
        tb[tid] = (tt >> 12) * (DIM * 4096) + (tt & 4095);
    }
    __syncthreads();

    for (int idx = tid; idx < RT * DIM; idx += 256) {
        int t = idx & 15, c = idx >> 4;
        zs[t * ZSTR + c] = batch[(size_t)tb[t] + (size_t)c * 4096];
    }
    __syncthreads();

    if (tid < RT) {
        float s = 0.0f;
        const float* zr = zs + tid * ZSTR;
        #pragma unroll 8
        for (int c = 0; c < DIM; c++)
            s = __fadd_rn(s, __fmul_rn(zr[c], zr[c]));
        zn[tid] = s;
    }
    __syncthreads();

    const int tg = tid & 7;
    const int cg = tid >> 3;

    int zrow[2], wrow[8];
    zrow[0] = tg * ZSTR; zrow[1] = (tg + 8) * ZSTR;
    #pragma unroll
    for (int j = 0; j < 8; j++) wrow[j] = (cg + 32 * j) * ZSTR;
    float znrv[2] = {zn[tg], zn[tg + 8]};

    float bestv[2] = {CUDART_INF_F, CUDART_INF_F};
    int   besti[2] = {0, 0};

    for (int chunk = 0; chunk < R_NCH; chunk++) {
        const int cb = chunk * R_CHUNK;
        __syncthreads();
        for (int f = tid; f < R_CHUNK * 32; f += 256) {
            int code = f >> 5, d4 = f & 31;
            float4 v = ((const float4*)(w + (size_t)(cb + code) * DIM))[d4];
            *(float4*)&ws[code * ZSTR + d4 * 4] = v;
        }
        if (tid < R_CHUNK) en[tid] = g_enorm[cb + tid];
        __syncthreads();

        unsigned long long acc[2][8];
        #pragma unroll
        for (int i = 0; i < 2; i++)
            #pragma unroll
            for (int j = 0; j < 8; j++) acc[i][j] = 0ull;

        #pragma unroll 2
        for (int d4 = 0; d4 < DIM / 4; d4++) {
            unsigned long long za0[2], za1[2];
            #pragma unroll
            for (int i = 0; i < 2; i++) {
                ulonglong2 v = *(const ulonglong2*)(zs + zrow[i] + d4 * 4);
                za0[i] = v.x; za1[i] = v.y;
            }
            #pragma unroll
            for (int j = 0; j < 8; j++) {
                ulonglong2 wv = *(const ulonglong2*)(ws + wrow[j] + d4 * 4);
                #pragma unroll
                for (int i = 0; i < 2; i++) {
                    acc[i][j] = ffma2(za0[i], wv.x, acc[i][j]);
                    acc[i][j] = ffma2(za1[i], wv.y, acc[i][j]);
                }
            }
        }
        #pragma unroll
        for (int j = 0; j < 8; j++) {
            const int code = cb + cg + 32 * j;
            const float ec = en[cg + 32 * j];
            #pragma unroll
            for (int i = 0; i < 2; i++) {
                float lo, hi;
                unpack2(acc[i][j], lo, hi);
                float dot = lo + hi;
                float s   = znrv[i] + ec;
                float dis = fmaf(-2.0f, dot, s);
                if (dis < bestv[i]) { bestv[i] = dis; besti[i] = code; }
            }
        }
    }

    __syncthreads();
    #pragma unroll
    for (int i = 0; i < 2; i++) {
        int t = tg + 8 * i;
        rv[t * 32 + cg] = bestv[i];
        ri[t * 32 + cg] = besti[i];
    }
    __syncthreads();
    if (tid < RT) {
        float bvv = rv[tid * 32];
        int   bii = ri[tid * 32];
        for (int c2 = 1; c2 < 32; c2++) {
            float v = rv[tid * 32 + c2];
            int  ii = ri[tid * 32 + c2];
            if (v < bvv || (v == bvv && ii < bii)) { bvv = v; bii = ii; }
        }
        if (tk[tid] >= 0) g_inds[tk[tid]] = bii;
    }
}

// ---------- output + loss ----------
__global__ void __launch_bounds__(256, 1)
vq_output(const float* __restrict__ batch, const float* __restrict__ w,
          float* __restrict__ out) {
    __shared__ float qsT[128 * 66];
    __shared__ int   si[64];
    __shared__ float red[512];

    const int tid = threadIdx.x, wid = tid >> 5, lane = tid & 31;
    const int n0 = blockIdx.x * 64, b = n0 >> 12, hw0 = n0 & 4095;

    if (tid < 64) si[tid] = g_inds[n0 + tid];
    __syncthreads();

    const float4* w4 = (const float4*)w;
    #pragma unroll
    for (int k = 0; k < 8; k++) {
        int f = tid + k * 256;
        int r = f >> 5, c4 = f & 31;
        float4 v = __ldg(&w4[(size_t)si[r] * 32 + c4]);
        int cb = c4 * 4;
        qsT[(cb + 0) * 66 + r] = v.x;
        qsT[(cb + 1) * 66 + r] = v.y;
        qsT[(cb + 2) * 66 + r] = v.z;
        qsT[(cb + 3) * 66 + r] = v.w;
    }
    __syncthreads();

    float s1 = 0.0f, s3 = 0.0f;
    #pragma unroll 4
    for (int it = 0; it < 16; it++) {
        int c = wid * 16 + it;
        size_t go = ((size_t)(b * 128 + c)) * 4096 + hw0 + 2 * lane;
        float2 z2 = *(const float2*)(batch + go);
        float q0 = qsT[c * 66 + 2 * lane];
        float q1 = qsT[c * 66 + 2 * lane + 1];
        float dq0 = q0 - z2.x, dq1 = q1 - z2.y;
        float ov0 = z2.x + dq0, ov1 = z2.y + dq1;
        float d30 = z2.x - ov0, d31 = z2.y - ov1;
        *(float2*)(out + go) = make_float2(ov0, ov1);
        s1 += dq0 * dq0 + dq1 * dq1;
        s3 += d30 * d30 + d31 * d31;
    }
    red[tid] = s1; red[256 + tid] = s3;
    __syncthreads();
    #pragma unroll
    for (int st = 128; st > 0; st >>= 1) {
        if (tid < st) { red[tid] += red[tid + st]; red[256 + tid] += red[256 + tid + st]; }
        __syncthreads();
    }
    if (tid == 0) {
        atomicAdd(&g_s1, (double)red[0]);
        atomicAdd(&g_s3, (double)red[256]);
    }
}

// ---------- finalize ----------
__global__ void vq_finalize(float* __restrict__ out, int out_size) {
    if (out_size <= TOT_ELEMS) return;
    const double inv = 1.0 / (double)TOT_ELEMS;
    float t1 = (float)(g_s1 * inv);
    float t3 = (float)(g_s3 * inv);
    out[TOT_ELEMS] = (t1 + t1) + t3 * 50.0f;
}

// ---------- launch ----------
extern "C" void kernel_launch(void* const* d_in, const int* in_sizes, int n_in,
                              void* d_out, int out_size) {
    const float* batch = (const float*)d_in[0];
    const float* wq    = (const float*)d_in[1];
    if (n_in >= 2 && in_sizes[0] == NUM_CODES * DIM) {
        const float* t = batch; batch = wq; wq = t;
    }
    float* out = (float*)d_out;

    const int SMEM_RECHECK = (RT * ZSTR + R_CHUNK * ZSTR + RT + R_CHUNK) * 4 + 128;

    cudaFuncSetAttribute(vq_tensor, cudaFuncAttributeMaxDynamicSharedMemorySize,
                         SMEM_TENSOR);
    cudaFuncSetAttribute(vq_fullB, cudaFuncAttributeMaxDynamicSharedMemorySize,
                         SMEM_RECHECK);

    vq_prep<<<320, 256>>>(wq);
    vq_tensor<<<N_TOKENS / TPC, 256, SMEM_TENSOR>>>(batch);
    vq_pairA<<<64, 256>>>(batch, wq);
    vq_fullB<<<512, 256, SMEM_RECHECK>>>(batch, wq);
    vq_output<<<N_TOKENS / 64, 256>>>(batch, wq, out);
    vq_finalize<<<1, 1>>>(out, out_size);
}

// round 12
// speedup vs baseline: 3.8825x; 1.1154x over previous
#include <cuda_runtime.h>
#include <cuda_fp16.h>
#include <math_constants.h>

#define NUM_CODES 2560
#define DIM       128
#define N_TOKENS  65536
#define TOT_ELEMS 8388608
#define TPC       256
#define CPC       64
#define N_CHUNKS  40
#define NSTAGE    3

#define RS          272
#define STAGE_B     (64 * RS)
#define OFF_BST     0
#define OFF_EN      69632                  // 256*RS (A temp) dominates 3*STAGE_B
#define OFF_ZN      (OFF_EN + NUM_CODES * 4)   // 79872
#define OFF_CNT     (OFF_ZN + 1024)            // 80896
#define OFF_CAND    (OFF_CNT + 1024)           // 81920
#define SMEM_TENSOR (OFF_CAND + 8192)          // 90112

__device__ __align__(16) float  g_enorm[NUM_CODES];
__device__ __align__(16) __half g_wh16[NUM_CODES * DIM];   // fp16(w * 4096)
__device__ int    g_enmax_i = 0;
__device__ int    g_inds[N_TOKENS];
__device__ int    g_tokA[N_TOKENS];                         // token | (cnt<<16)
__device__ __align__(16) unsigned short g_candA[N_TOKENS * 16];
__device__ int    g_listB[N_TOKENS];
__device__ int    g_nA, g_nB;
__device__ double g_s1, g_s3;

// ---------- helpers ----------
__device__ __forceinline__ unsigned smem_u32(const void* p) {
    unsigned a;
    asm("{ .reg .u64 t; cvta.to.shared.u64 t, %1; cvt.u32.u64 %0, t; }" : "=r"(a) : "l"(p));
    return a;
}
__device__ __forceinline__ unsigned lds32(unsigned a) {
    unsigned v;
    asm volatile("ld.shared.b32 %0, [%1];" : "=r"(v) : "r"(a));
    return v;
}
__device__ __forceinline__ float2 lds64f(unsigned a) {
    float2 v;
    asm volatile("ld.shared.v2.f32 {%0, %1}, [%2];" : "=f"(v.x), "=f"(v.y) : "r"(a));
    return v;
}
__device__ __forceinline__ void mma_f16(float* c, const unsigned* a,
                                        unsigned b0, unsigned b1) {
    asm volatile(
        "mma.sync.aligned.m16n8k16.row.col.f32.f16.f16.f32 "
        "{%0,%1,%2,%3}, {%4,%5,%6,%7}, {%8,%9}, {%0,%1,%2,%3};"
        : "+f"(c[0]), "+f"(c[1]), "+f"(c[2]), "+f"(c[3])
        : "r"(a[0]), "r"(a[1]), "r"(a[2]), "r"(a[3]), "r"(b0), "r"(b1));
}

// ---------- prep: enorm (+max) + fp16(w*4096) ----------
__global__ void vq_prep(const float* __restrict__ w) {
    int gtid = blockIdx.x * blockDim.x + threadIdx.x;
    if (gtid == 0) { g_s1 = 0.0; g_s3 = 0.0; g_nA = 0; g_nB = 0; }
    int gw = gtid >> 5, lane = threadIdx.x & 31;
    if (gw < NUM_CODES) {
        const float* row = w + (size_t)gw * DIM;
        float s = 0.0f;
        #pragma unroll
        for (int k = lane; k < DIM; k += 32) {
            float v = row[k];
            s = __fadd_rn(s, __fmul_rn(v, v));
        }
        #pragma unroll
        for (int off = 16; off > 0; off >>= 1) s += __shfl_xor_sync(~0u, s, off);
        if (lane == 0) {
            g_enorm[gw] = s;
            atomicMax(&g_enmax_i, __float_as_int(s));
        }
    }
    int stride = gridDim.x * blockDim.x;
    for (int i = gtid; i < NUM_CODES * DIM; i += stride)
        g_wh16[i] = __float2half_rn(w[i] * 4096.0f);
}

// ---------- tensor pass ----------
__device__ __forceinline__ void issue_chunk(unsigned sb, int tid, int cn, int st) {
    const uint4* gh = ((const uint4*)g_wh16) + (size_t)cn * 1024;
    unsigned base = sb + OFF_BST + st * STAGE_B;
    #pragma unroll
    for (int i = 0; i < 4; i++) {
        int f = tid + i * 256;
        unsigned d = base + (f >> 4) * RS + (f & 15) * 16;
        asm volatile("cp.async.cg.shared.global [%0], [%1], 16;" :: "r"(d), "l"(gh + f));
    }
}

__global__ void __launch_bounds__(256, 1)
vq_tensor(const float* __restrict__ batch) {
    extern __shared__ char smem[];
    const unsigned sb = smem_u32(smem);
    float*          zn_s  = (float*)(smem + OFF_ZN);
    int*            scnt  = (int*)(smem + OFF_CNT);
    unsigned short* scand = (unsigned short*)(smem + OFF_CAND);

    const int tid = threadIdx.x, wid = tid >> 5, lane = tid & 31;
    const int n0 = blockIdx.x * TPC, b = n0 >> 12, hw0 = n0 & 4095;
    const float* zbase = batch + (size_t)b * (DIM * 4096) + hw0;
    const float enmax = __int_as_float(g_enmax_i);

    // prologue: token tid: znorm (R1 order) + fp16(z*16) into A temp
    {
        const float* zp = zbase + tid;
        float acc = 0.0f;
        #pragma unroll 4
        for (int c = 0; c < DIM; c += 2) {
            float z0 = zp[(size_t)c * 4096];
            float z1 = zp[(size_t)(c + 1) * 4096];
            acc = __fadd_rn(acc, __fmul_rn(z0, z0));
            acc = __fadd_rn(acc, __fmul_rn(z1, z1));
            __half h0 = __float2half_rn(z0 * 16.0f);
            __half h1 = __float2half_rn(z1 * 16.0f);
            unsigned hp = (unsigned)__half_as_ushort(h0) |
                          ((unsigned)__half_as_ushort(h1) << 16);
            *(unsigned*)(smem + OFF_BST + tid * RS + c * 2) = hp;
        }
        zn_s[tid] = acc;
        scnt[tid] = 0;
    }
    for (int i = tid; i < NUM_CODES; i += 256)
        ((float*)(smem + OFF_EN))[i] = g_enorm[i];
    __syncthreads();

    const unsigned Rb = wid * 32 + (lane >> 2);
    const unsigned Cb = (lane & 3) * 2;
    unsigned Ah[2][8][4];
    #pragma unroll
    for (int mt = 0; mt < 2; mt++)
        #pragma unroll
        for (int ks = 0; ks < 8; ks++) {
            unsigned a = sb + OFF_BST + (Rb + mt * 16) * RS + (ks * 16 + Cb) * 2;
            Ah[mt][ks][0] = lds32(a);
            Ah[mt][ks][1] = lds32(a + 8 * RS);
            Ah[mt][ks][2] = lds32(a + 16);
            Ah[mt][ks][3] = lds32(a + 8 * RS + 16);
        }
    float znr[4], TT[4];
    #pragma unroll
    for (int j = 0; j < 4; j++) {
        znr[j] = zn_s[Rb + j * 8];
        TT[j]  = 2.0f * (1.0e-3f * sqrtf(znr[j] * enmax) + 6.0e-5f);
    }
    __syncthreads();   // A temp fully consumed before B stages overwrite it

    issue_chunk(sb, tid, 0, 0);
    asm volatile("cp.async.commit_group;" ::: "memory");
    issue_chunk(sb, tid, 1, 1);
    asm volatile("cp.async.commit_group;" ::: "memory");
    issue_chunk(sb, tid, 2, 2);
    asm volatile("cp.async.commit_group;" ::: "memory");

    float acc[2][8][4];
    #pragma unroll
    for (int mt = 0; mt < 2; mt++)
        #pragma unroll
        for (int nt = 0; nt < 8; nt++)
            #pragma unroll
            for (int q = 0; q < 4; q++) acc[mt][nt][q] = 0.0f;

    float v1[4] = {CUDART_INF_F, CUDART_INF_F, CUDART_INF_F, CUDART_INF_F};

    const unsigned bfrag_base = sb + OFF_BST + (lane >> 2) * RS + Cb * 2;
    const float DS = -3.0517578125e-05f;   // -2 * 2^-16

    for (int cn = 0; cn < N_CHUNKS; cn++) {
        asm volatile("cp.async.wait_group 2;" ::: "memory");
        __syncthreads();
        const unsigned sbase = (unsigned)(cn % NSTAGE) * STAGE_B;

        #pragma unroll
        for (int ks = 0; ks < 8; ks++) {
            #pragma unroll
            for (int nt = 0; nt < 8; nt++) {
                unsigned ba = bfrag_base + sbase + nt * 8 * RS + ks * 32;
                unsigned b0 = lds32(ba), b1 = lds32(ba + 16);
                mma_f16(acc[0][nt], Ah[0][ks], b0, b1);
                mma_f16(acc[1][nt], Ah[1][ks], b0, b1);
            }
        }
        __syncthreads();
        if (cn + NSTAGE < N_CHUNKS) issue_chunk(sb, tid, cn + NSTAGE, cn % NSTAGE);
        asm volatile("cp.async.commit_group;" ::: "memory");

        // ---- distances in place ----
        #pragma unroll
        for (int nt = 0; nt < 8; nt++) {
            const int code0 = cn * CPC + nt * 8 + (int)Cb;
            float2 e = lds64f(sb + OFF_EN + (unsigned)code0 * 4);
            #pragma unroll
            for (int mt = 0; mt < 2; mt++) {
                acc[mt][nt][0] = fmaf(DS, acc[mt][nt][0], znr[2 * mt] + e.x);
                acc[mt][nt][1] = fmaf(DS, acc[mt][nt][1], znr[2 * mt] + e.y);
                acc[mt][nt][2] = fmaf(DS, acc[mt][nt][2], znr[2 * mt + 1] + e.x);
                acc[mt][nt][3] = fmaf(DS, acc[mt][nt][3], znr[2 * mt + 1] + e.y);
            }
        }
        // ---- per slot: lane min -> quad (token-global) min -> collect ----
        #pragma unroll
        for (int sl = 0; sl < 4; sl++) {
            const int mt = sl >> 1, half = sl & 1;
            float m = fminf(acc[mt][0][2 * half], acc[mt][0][2 * half + 1]);
            #pragma unroll
            for (int nt = 1; nt < 8; nt++)
                m = fminf(m, fminf(acc[mt][nt][2 * half], acc[mt][nt][2 * half + 1]));
            float mq = m;
            mq = fminf(mq, __shfl_xor_sync(~0u, mq, 1));
            mq = fminf(mq, __shfl_xor_sync(~0u, mq, 2));
            v1[sl] = fminf(v1[sl], mq);
            float lim = v1[sl] + TT[sl];
            if (m < lim) {
                int tl = (int)Rb + sl * 8;
                #pragma unroll
                for (int nt = 0; nt < 8; nt++) {
                    int code0 = cn * CPC + nt * 8 + (int)Cb;
                    float dA = acc[mt][nt][2 * half];
                    float dB = acc[mt][nt][2 * half + 1];
                    if (dA < lim) {
                        int p = atomicAdd(&scnt[tl], 1);
                        if (p < 16) scand[tl * 16 + p] = (unsigned short)code0;
                    }
                    if (dB < lim) {
                        int p = atomicAdd(&scnt[tl], 1);
                        if (p < 16) scand[tl * 16 + p] = (unsigned short)(code0 + 1);
                    }
                }
            }
        }
        // ---- reset acc ----
        #pragma unroll
        for (int mt = 0; mt < 2; mt++)
            #pragma unroll
            for (int nt = 0; nt < 8; nt++) {
                acc[mt][nt][0] = 0.0f; acc[mt][nt][1] = 0.0f;
                acc[mt][nt][2] = 0.0f; acc[mt][nt][3] = 0.0f;
            }
    }

    // ---- finale: classify per token ----
    __syncthreads();
    if (tid < 256) {
        int c = scnt[tid];
        int token = n0 + tid;
        if (c == 1) {
            g_inds[token] = scand[tid * 16];
        } else if (c <= 16) {
            int p = atomicAdd(&g_nA, 1);
            g_tokA[p] = token | (c << 16);
            for (int i = 0; i < c; i++)
                g_candA[p * 16 + i] = scand[tid * 16 + i];
        } else {
            int p = atomicAdd(&g_nB, 1);
            g_listB[p] = token;
        }
    }
}

// ---------- resolve: exact R1-numerics over collected candidates ----------
__global__ void __launch_bounds__(256, 1)
vq_resolve(const float* __restrict__ batch, const float* __restrict__ w) {
    const int nA = *(volatile int*)&g_nA;
    for (int k = blockIdx.x * 256 + threadIdx.x; k < nA; k += gridDim.x * 256) {
        int word = g_tokA[k];
        int token = word & 0xFFFF;
        int cnt = word >> 16;
        const float* zp = batch + (size_t)(token >> 12) * (DIM * 4096) + (token & 4095);

        // znorm: exact R1 sequential chain
        float zn = 0.0f;
        #pragma unroll 4
        for (int c = 0; c < DIM; c += 2) {
            float z0 = zp[(size_t)c * 4096];
            float z1 = zp[(size_t)(c + 1) * 4096];
            zn = __fadd_rn(zn, __fmul_rn(z0, z0));
            zn = __fadd_rn(zn, __fmul_rn(z1, z1));
        }

        float bv = CUDART_INF_F;
        int   bi = 0x7FFFFFFF;
        for (int base = 0; base < cnt; base += 4) {
            int nc = cnt - base; if (nc > 4) nc = 4;
            int idx[4];
            const float* wr[4];
            float lo[4] = {0.f, 0.f, 0.f, 0.f}, hi[4] = {0.f, 0.f, 0.f, 0.f};
            #pragma unroll
            for (int q = 0; q < 4; q++) {
                idx[q] = g_candA[k * 16 + base + ((q < nc) ? q : 0)];
                wr[q] = w + (size_t)idx[q] * DIM;
            }
            #pragma unroll 2
            for (int c = 0; c < DIM; c += 2) {
                float z0 = zp[(size_t)c * 4096];
                float z1 = zp[(size_t)(c + 1) * 4096];
                #pragma unroll
                for (int q = 0; q < 4; q++) {
                    lo[q] = fmaf(z0, __ldg(&wr[q][c]), lo[q]);       // R1 even chain
                    hi[q] = fmaf(z1, __ldg(&wr[q][c + 1]), hi[q]);   // R1 odd chain
                }
            }
            for (int q = 0; q < nc; q++) {
                float d = fmaf(-2.0f, __fadd_rn(lo[q], hi[q]),
                               __fadd_rn(zn, g_enorm[idx[q]]));
                if (d < bv || (d == bv && idx[q] < bi)) { bv = d; bi = idx[q]; }
            }
        }
        g_inds[token] = bi;
    }
}

// ---------- fullB: warp-per-token exact full scan (overflow only; expected ~0) ----------
__global__ void __launch_bounds__(256, 1)
vq_fullB(const float* __restrict__ batch, const float* __restrict__ w) {
    const int nB = *(volatile int*)&g_nB;
    __shared__ float zsm[8][128];

    const int tid = threadIdx.x, wid = tid >> 5, lane = tid & 31;

    for (int k = blockIdx.x * 8 + wid; k < nB; k += gridDim.x * 8) {
        int token = g_listB[k];
        const float* zp = batch + (size_t)(token >> 12) * (DIM * 4096) + (token & 4095);
        #pragma unroll
        for (int c = lane; c < DIM; c += 32)
            zsm[wid][c] = zp[(size_t)c * 4096];
        __syncwarp();

        float zn = 0.0f;
        #pragma unroll 8
        for (int c = 0; c < DIM; c++)
            zn = __fadd_rn(zn, __fmul_rn(zsm[wid][c], zsm[wid][c]));

        float bv = CUDART_INF_F;
        int   bi = 0;
        for (int kk = 0; kk < NUM_CODES / 32; kk++) {
            int code = lane + kk * 32;
            const float* wr = w + (size_t)code * DIM;
            float lo = 0.0f, hi = 0.0f;
            #pragma unroll 8
            for (int c = 0; c < DIM; c += 4) {
                lo = fmaf(zsm[wid][c],     __ldg(&wr[c]),     lo);
                hi = fmaf(zsm[wid][c + 1], __ldg(&wr[c + 1]), hi);
                lo = fmaf(zsm[wid][c + 2], __ldg(&wr[c + 2]), lo);
                hi = fmaf(zsm[wid][c + 3], __ldg(&wr[c + 3]), hi);
            }
            float dis = fmaf(-2.0f, __fadd_rn(lo, hi), __fadd_rn(zn, __ldg(&g_enorm[code])));
            if (dis < bv) { bv = dis; bi = code; }
        }
        #pragma unroll
        for (int off = 16; off > 0; off >>= 1) {
            float ov = __shfl_xor_sync(~0u, bv, off);
            int   oi = __shfl_xor_sync(~0u, bi, off);
            if (ov < bv || (ov == bv && oi < bi)) { bv = ov; bi = oi; }
        }
        if (lane == 0) g_inds[token] = bi;
        __syncwarp();
    }
}

// ---------- output + loss ----------
__global__ void __launch_bounds__(256, 1)
vq_output(const float* __restrict__ batch, const float* __restrict__ w,
          float* __restrict__ out) {
    __shared__ float qsT[128 * 66];
    __shared__ int   si[64];
    __shared__ float red[512];

    const int tid = threadIdx.x, wid = tid >> 5, lane = tid & 31;
    const int n0 = blockIdx.x * 64, b = n0 >> 12, hw0 = n0 & 4095;

    if (tid < 64) si[tid] = g_inds[n0 + tid];
    __syncthreads();

    const float4* w4 = (const float4*)w;
    #pragma unroll
    for (int k = 0; k < 8; k++) {
        int f = tid + k * 256;
        int r = f >> 5, c4 = f & 31;
        float4 v = __ldg(&w4[(size_t)si[r] * 32 + c4]);
        int cb = c4 * 4;
        qsT[(cb + 0) * 66 + r] = v.x;
        qsT[(cb + 1) * 66 + r] = v.y;
        qsT[(cb + 2) * 66 + r] = v.z;
        qsT[(cb + 3) * 66 + r] = v.w;
    }
    __syncthreads();

    float s1 = 0.0f, s3 = 0.0f;
    #pragma unroll 4
    for (int it = 0; it < 16; it++) {
        int c = wid * 16 + it;
        size_t go = ((size_t)(b * 128 + c)) * 4096 + hw0 + 2 * lane;
        float2 z2 = *(const float2*)(batch + go);
        float q0 = qsT[c * 66 + 2 * lane];
        float q1 = qsT[c * 66 + 2 * lane + 1];
        float dq0 = q0 - z2.x, dq1 = q1 - z2.y;
        float ov0 = z2.x + dq0, ov1 = z2.y + dq1;
        float d30 = z2.x - ov0, d31 = z2.y - ov1;
        *(float2*)(out + go) = make_float2(ov0, ov1);
        s1 += dq0 * dq0 + dq1 * dq1;
        s3 += d30 * d30 + d31 * d31;
    }
    red[tid] = s1; red[256 + tid] = s3;
    __syncthreads();
    #pragma unroll
    for (int st = 128; st > 0; st >>= 1) {
        if (tid < st) { red[tid] += red[tid + st]; red[256 + tid] += red[256 + tid + st]; }
        __syncthreads();
    }
    if (tid == 0) {
        atomicAdd(&g_s1, (double)red[0]);
        atomicAdd(&g_s3, (double)red[256]);
    }
}

// ---------- finalize ----------
__global__ void vq_finalize(float* __restrict__ out, int out_size) {
    if (out_size <= TOT_ELEMS) return;
    const double inv = 1.0 / (double)TOT_ELEMS;
    float t1 = (float)(g_s1 * inv);
    float t3 = (float)(g_s3 * inv);
    out[TOT_ELEMS] = (t1 + t1) + t3 * 50.0f;
}

// ---------- launch ----------
extern "C" void kernel_launch(void* const* d_in, const int* in_sizes, int n_in,
                              void* d_out, int out_size) {
    const float* batch = (const float*)d_in[0];
    const float* wq    = (const float*)d_in[1];
    if (n_in >= 2 && in_sizes[0] == NUM_CODES * DIM) {
        const float* t = batch; batch = wq; wq = t;
    }
    float* out = (float*)d_out;

    cudaFuncSetAttribute(vq_tensor, cudaFuncAttributeMaxDynamicSharedMemorySize,
                         SMEM_TENSOR);

    vq_prep<<<320, 256>>>(wq);
    vq_tensor<<<N_TOKENS / TPC, 256, SMEM_TENSOR>>>(batch);
    vq_resolve<<<128, 256>>>(batch, wq);
    vq_fullB<<<32, 256>>>(batch, wq);
    vq_output<<<N_TOKENS / 64, 256>>>(batch, wq, out);
    vq_finalize<<<1, 1>>>(out, out_size);
}

// round 13
// speedup vs baseline: 4.2012x; 1.0821x over previous
#include <cuda_runtime.h>
#include <cuda_fp16.h>
#include <math_constants.h>

#define NUM_CODES 2560
#define DIM       128
#define N_TOKENS  65536
#define TOT_ELEMS 8388608
#define TPC       256
#define CPC       64
#define N_CHUNKS  40
#define NSTAGE    3

#define RS          272
#define STAGE_B     (64 * RS)
#define OFF_BST     0
#define OFF_EN      69632                  // 256*RS (A temp) dominates 3*STAGE_B
#define OFF_ZN      (OFF_EN + NUM_CODES * 4)   // 79872
#define OFF_CNT     (OFF_ZN + 1024)            // 80896
#define OFF_CAND    (OFF_CNT + 1024)           // 81920
#define SMEM_TENSOR (OFF_CAND + 8192)          // 90112

__device__ __align__(16) float  g_enorm[NUM_CODES];
__device__ __align__(16) __half g_wh16[NUM_CODES * DIM];   // fp16(w * 4096)
__device__ int    g_enmax_i = 0;
__device__ int    g_inds[N_TOKENS];
__device__ int    g_tokA[N_TOKENS];                         // token | (cnt<<16)
__device__ __align__(16) unsigned short g_candA[N_TOKENS * 16];
__device__ int    g_listB[N_TOKENS];
__device__ int    g_nA, g_nB;
__device__ double g_s1, g_s3;

// ---------- helpers ----------
__device__ __forceinline__ unsigned smem_u32(const void* p) {
    unsigned a;
    asm("{ .reg .u64 t; cvta.to.shared.u64 t, %1; cvt.u32.u64 %0, t; }" : "=r"(a) : "l"(p));
    return a;
}
__device__ __forceinline__ unsigned lds32(unsigned a) {
    unsigned v;
    asm volatile("ld.shared.b32 %0, [%1];" : "=r"(v) : "r"(a));
    return v;
}
__device__ __forceinline__ float2 lds64f(unsigned a) {
    float2 v;
    asm volatile("ld.shared.v2.f32 {%0, %1}, [%2];" : "=f"(v.x), "=f"(v.y) : "r"(a));
    return v;
}
__device__ __forceinline__ void mma_f16(float* c, const unsigned* a,
                                        unsigned b0, unsigned b1) {
    asm volatile(
        "mma.sync.aligned.m16n8k16.row.col.f32.f16.f16.f32 "
        "{%0,%1,%2,%3}, {%4,%5,%6,%7}, {%8,%9}, {%0,%1,%2,%3};"
        : "+f"(c[0]), "+f"(c[1]), "+f"(c[2]), "+f"(c[3])
        : "r"(a[0]), "r"(a[1]), "r"(a[2]), "r"(a[3]), "r"(b0), "r"(b1));
}

// ---------- prep: enorm (+max) + fp16(w*4096) ----------
__global__ void vq_prep(const float* __restrict__ w) {
    int gtid = blockIdx.x * blockDim.x + threadIdx.x;
    if (gtid == 0) { g_s1 = 0.0; g_s3 = 0.0; g_nA = 0; g_nB = 0; }
    int gw = gtid >> 5, lane = threadIdx.x & 31;
    if (gw < NUM_CODES) {
        const float* row = w + (size_t)gw * DIM;
        float s = 0.0f;
        #pragma unroll
        for (int k = lane; k < DIM; k += 32) {
            float v = row[k];
            s = __fadd_rn(s, __fmul_rn(v, v));
        }
        #pragma unroll
        for (int off = 16; off > 0; off >>= 1) s += __shfl_xor_sync(~0u, s, off);
        if (lane == 0) {
            g_enorm[gw] = s;
            atomicMax(&g_enmax_i, __float_as_int(s));
        }
    }
    int stride = gridDim.x * blockDim.x;
    for (int i = gtid; i < NUM_CODES * DIM; i += stride)
        g_wh16[i] = __float2half_rn(w[i] * 4096.0f);
}

// ---------- tensor pass: 512 threads, 16 warps, warp tile 16 tokens x 64 codes ----------
__device__ __forceinline__ void issue_chunk(unsigned sb, int tid, int cn, int st) {
    const uint4* gh = ((const uint4*)g_wh16) + (size_t)cn * 1024;
    unsigned base = sb + OFF_BST + st * STAGE_B;
    #pragma unroll
    for (int i = 0; i < 2; i++) {
        int f = tid + i * 512;
        unsigned d = base + (f >> 4) * RS + (f & 15) * 16;
        asm volatile("cp.async.cg.shared.global [%0], [%1], 16;" :: "r"(d), "l"(gh + f));
    }
}

__global__ void __launch_bounds__(512, 1)
vq_tensor(const float* __restrict__ batch) {
    extern __shared__ char smem[];
    const unsigned sb = smem_u32(smem);
    float*          zn_s  = (float*)(smem + OFF_ZN);
    int*            scnt  = (int*)(smem + OFF_CNT);
    unsigned short* scand = (unsigned short*)(smem + OFF_CAND);

    const int tid = threadIdx.x, wid = tid >> 5, lane = tid & 31;
    const int n0 = blockIdx.x * TPC, b = n0 >> 12, hw0 = n0 & 4095;
    const float* zbase = batch + (size_t)b * (DIM * 4096) + hw0;
    const float enmax = __int_as_float(g_enmax_i);

    // prologue: threads 0-255: token tid: znorm (R1 order) + fp16(z*16) into A temp
    if (tid < 256) {
        const float* zp = zbase + tid;
        float acc = 0.0f;
        #pragma unroll 4
        for (int c = 0; c < DIM; c += 2) {
            float z0 = zp[(size_t)c * 4096];
            float z1 = zp[(size_t)(c + 1) * 4096];
            acc = __fadd_rn(acc, __fmul_rn(z0, z0));
            acc = __fadd_rn(acc, __fmul_rn(z1, z1));
            __half h0 = __float2half_rn(z0 * 16.0f);
            __half h1 = __float2half_rn(z1 * 16.0f);
            unsigned hp = (unsigned)__half_as_ushort(h0) |
                          ((unsigned)__half_as_ushort(h1) << 16);
            *(unsigned*)(smem + OFF_BST + tid * RS + c * 2) = hp;
        }
        zn_s[tid] = acc;
        scnt[tid] = 0;
    }
    for (int i = tid; i < NUM_CODES; i += 512)
        ((float*)(smem + OFF_EN))[i] = g_enorm[i];
    __syncthreads();

    // warp tile: tokens [wid*16, wid*16+16); lane row r = lane>>2, tokens Rb, Rb+8
    const unsigned Rb = wid * 16 + (lane >> 2);
    const unsigned Cb = (lane & 3) * 2;
    unsigned Ah[8][4];
    #pragma unroll
    for (int ks = 0; ks < 8; ks++) {
        unsigned a = sb + OFF_BST + Rb * RS + (ks * 16 + Cb) * 2;
        Ah[ks][0] = lds32(a);
        Ah[ks][1] = lds32(a + 8 * RS);
        Ah[ks][2] = lds32(a + 16);
        Ah[ks][3] = lds32(a + 8 * RS + 16);
    }
    float znr[2], TT[2];
    #pragma unroll
    for (int j = 0; j < 2; j++) {
        znr[j] = zn_s[Rb + j * 8];
        TT[j]  = 2.0f * (1.0e-3f * sqrtf(znr[j] * enmax) + 6.0e-5f);
    }
    __syncthreads();   // A temp fully consumed before B stages overwrite it

    issue_chunk(sb, tid, 0, 0);
    asm volatile("cp.async.commit_group;" ::: "memory");
    issue_chunk(sb, tid, 1, 1);
    asm volatile("cp.async.commit_group;" ::: "memory");
    issue_chunk(sb, tid, 2, 2);
    asm volatile("cp.async.commit_group;" ::: "memory");

    float acc[8][4];
    #pragma unroll
    for (int nt = 0; nt < 8; nt++)
        #pragma unroll
        for (int q = 0; q < 4; q++) acc[nt][q] = 0.0f;

    float v1[2] = {CUDART_INF_F, CUDART_INF_F};

    const unsigned bfrag_base = sb + OFF_BST + (lane >> 2) * RS + Cb * 2;
    const float DS = -3.0517578125e-05f;   // -2 * 2^-16

    for (int cn = 0; cn < N_CHUNKS; cn++) {
        asm volatile("cp.async.wait_group 2;" ::: "memory");
        __syncthreads();
        const unsigned sbase = (unsigned)(cn % NSTAGE) * STAGE_B;

        #pragma unroll
        for (int ks = 0; ks < 8; ks++) {
            #pragma unroll
            for (int nt = 0; nt < 8; nt++) {
                unsigned ba = bfrag_base + sbase + nt * 8 * RS + ks * 32;
                unsigned b0 = lds32(ba), b1 = lds32(ba + 16);
                mma_f16(acc[nt], Ah[ks], b0, b1);
            }
        }
        __syncthreads();
        if (cn + NSTAGE < N_CHUNKS) issue_chunk(sb, tid, cn + NSTAGE, cn % NSTAGE);
        asm volatile("cp.async.commit_group;" ::: "memory");

        // ---- distances in place ----
        #pragma unroll
        for (int nt = 0; nt < 8; nt++) {
            const int code0 = cn * CPC + nt * 8 + (int)Cb;
            float2 e = lds64f(sb + OFF_EN + (unsigned)code0 * 4);
            acc[nt][0] = fmaf(DS, acc[nt][0], znr[0] + e.x);
            acc[nt][1] = fmaf(DS, acc[nt][1], znr[0] + e.y);
            acc[nt][2] = fmaf(DS, acc[nt][2], znr[1] + e.x);
            acc[nt][3] = fmaf(DS, acc[nt][3], znr[1] + e.y);
        }
        // ---- per slot: lane min -> quad (token-global) min -> collect ----
        #pragma unroll
        for (int sl = 0; sl < 2; sl++) {
            float m = fminf(acc[0][2 * sl], acc[0][2 * sl + 1]);
            #pragma unroll
            for (int nt = 1; nt < 8; nt++)
                m = fminf(m, fminf(acc[nt][2 * sl], acc[nt][2 * sl + 1]));
            float mq = m;
            mq = fminf(mq, __shfl_xor_sync(~0u, mq, 1));
            mq = fminf(mq, __shfl_xor_sync(~0u, mq, 2));
            v1[sl] = fminf(v1[sl], mq);
            float lim = v1[sl] + TT[sl];
            if (m < lim) {
                int tl = (int)Rb + sl * 8;
                #pragma unroll
                for (int nt = 0; nt < 8; nt++) {
                    int code0 = cn * CPC + nt * 8 + (int)Cb;
                    float dA = acc[nt][2 * sl];
                    float dB = acc[nt][2 * sl + 1];
                    if (dA < lim) {
                        int p = atomicAdd(&scnt[tl], 1);
                        if (p < 16) scand[tl * 16 + p] = (unsigned short)code0;
                    }
                    if (dB < lim) {
                        int p = atomicAdd(&scnt[tl], 1);
                        if (p < 16) scand[tl * 16 + p] = (unsigned short)(code0 + 1);
                    }
                }
            }
        }
        // ---- reset acc ----
        #pragma unroll
        for (int nt = 0; nt < 8; nt++) {
            acc[nt][0] = 0.0f; acc[nt][1] = 0.0f;
            acc[nt][2] = 0.0f; acc[nt][3] = 0.0f;
        }
    }

    // ---- finale: classify per token ----
    __syncthreads();
    if (tid < 256) {
        int c = scnt[tid];
        int token = n0 + tid;
        if (c == 1) {
            g_inds[token] = scand[tid * 16];
        } else if (c <= 16) {
            int p = atomicAdd(&g_nA, 1);
            g_tokA[p] = token | (c << 16);
            for (int i = 0; i < c; i++)
                g_candA[p * 16 + i] = scand[tid * 16 + i];
        } else {
            int p = atomicAdd(&g_nB, 1);
            g_listB[p] = token;
        }
    }
}

// ---------- resolve: exact R1-numerics over collected candidates ----------
__global__ void __launch_bounds__(256, 1)
vq_resolve(const float* __restrict__ batch, const float* __restrict__ w) {
    const int nA = *(volatile int*)&g_nA;
    for (int k = blockIdx.x * 256 + threadIdx.x; k < nA; k += gridDim.x * 256) {
        int word = g_tokA[k];
        int token = word & 0xFFFF;
        int cnt = word >> 16;
        const float* zp = batch + (size_t)(token >> 12) * (DIM * 4096) + (token & 4095);

        float zn = 0.0f;
        #pragma unroll 4
        for (int c = 0; c < DIM; c += 2) {
            float z0 = zp[(size_t)c * 4096];
            float z1 = zp[(size_t)(c + 1) * 4096];
            zn = __fadd_rn(zn, __fmul_rn(z0, z0));
            zn = __fadd_rn(zn, __fmul_rn(z1, z1));
        }

        float bv = CUDART_INF_F;
        int   bi = 0x7FFFFFFF;
        for (int base = 0; base < cnt; base += 4) {
            int nc = cnt - base; if (nc > 4) nc = 4;
            int idx[4];
            const float* wr[4];
            float lo[4] = {0.f, 0.f, 0.f, 0.f}, hi[4] = {0.f, 0.f, 0.f, 0.f};
            #pragma unroll
            for (int q = 0; q < 4; q++) {
                idx[q] = g_candA[k * 16 + base + ((q < nc) ? q : 0)];
                wr[q] = w + (size_t)idx[q] * DIM;
            }
            #pragma unroll 2
            for (int c = 0; c < DIM; c += 2) {
                float z0 = zp[(size_t)c * 4096];
                float z1 = zp[(size_t)(c + 1) * 4096];
                #pragma unroll
                for (int q = 0; q < 4; q++) {
                    lo[q] = fmaf(z0, __ldg(&wr[q][c]), lo[q]);       // R1 even chain
                    hi[q] = fmaf(z1, __ldg(&wr[q][c + 1]), hi[q]);   // R1 odd chain
                }
            }
            for (int q = 0; q < nc; q++) {
                float d = fmaf(-2.0f, __fadd_rn(lo[q], hi[q]),
                               __fadd_rn(zn, g_enorm[idx[q]]));
                if (d < bv || (d == bv && idx[q] < bi)) { bv = d; bi = idx[q]; }
            }
        }
        g_inds[token] = bi;
    }
}

// ---------- fullB: warp-per-token exact full scan (overflow only) ----------
__global__ void __launch_bounds__(256, 1)
vq_fullB(const float* __restrict__ batch, const float* __restrict__ w) {
    const int nB = *(volatile int*)&g_nB;
    __shared__ float zsm[8][128];

    const int tid = threadIdx.x, wid = tid >> 5, lane = tid & 31;

    for (int k = blockIdx.x * 8 + wid; k < nB; k += gridDim.x * 8) {
        int token = g_listB[k];
        const float* zp = batch + (size_t)(token >> 12) * (DIM * 4096) + (token & 4095);
        #pragma unroll
        for (int c = lane; c < DIM; c += 32)
            zsm[wid][c] = zp[(size_t)c * 4096];
        __syncwarp();

        float zn = 0.0f;
        #pragma unroll 8
        for (int c = 0; c < DIM; c++)
            zn = __fadd_rn(zn, __fmul_rn(zsm[wid][c], zsm[wid][c]));

        float bv = CUDART_INF_F;
        int   bi = 0;
        for (int kk = 0; kk < NUM_CODES / 32; kk++) {
            int code = lane + kk * 32;
            const float* wr = w + (size_t)code * DIM;
            float lo = 0.0f, hi = 0.0f;
            #pragma unroll 8
            for (int c = 0; c < DIM; c += 4) {
                lo = fmaf(zsm[wid][c],     __ldg(&wr[c]),     lo);
                hi = fmaf(zsm[wid][c + 1], __ldg(&wr[c + 1]), hi);
                lo = fmaf(zsm[wid][c + 2], __ldg(&wr[c + 2]), lo);
                hi = fmaf(zsm[wid][c + 3], __ldg(&wr[c + 3]), hi);
            }
            float dis = fmaf(-2.0f, __fadd_rn(lo, hi), __fadd_rn(zn, __ldg(&g_enorm[code])));
            if (dis < bv) { bv = dis; bi = code; }
        }
        #pragma unroll
        for (int off = 16; off > 0; off >>= 1) {
            float ov = __shfl_xor_sync(~0u, bv, off);
            int   oi = __shfl_xor_sync(~0u, bi, off);
            if (ov < bv || (ov == bv && oi < bi)) { bv = ov; bi = oi; }
        }
        if (lane == 0) g_inds[token] = bi;
        __syncwarp();
    }
}

// ---------- output + loss ----------
__global__ void __launch_bounds__(256, 1)
vq_output(const float* __restrict__ batch, const float* __restrict__ w,
          float* __restrict__ out) {
    __shared__ float qsT[128 * 66];
    __shared__ int   si[64];
    __shared__ float red[512];

    const int tid = threadIdx.x, wid = tid >> 5, lane = tid & 31;
    const int n0 = blockIdx.x * 64, b = n0 >> 12, hw0 = n0 & 4095;

    if (tid < 64) si[tid] = g_inds[n0 + tid];
    __syncthreads();

    const float4* w4 = (const float4*)w;
    #pragma unroll
    for (int k = 0; k < 8; k++) {
        int f = tid + k * 256;
        int r = f >> 5, c4 = f & 31;
        float4 v = __ldg(&w4[(size_t)si[r] * 32 + c4]);
        int cb = c4 * 4;
        qsT[(cb + 0) * 66 + r] = v.x;
        qsT[(cb + 1) * 66 + r] = v.y;
        qsT[(cb + 2) * 66 + r] = v.z;
        qsT[(cb + 3) * 66 + r] = v.w;
    }
    __syncthreads();

    float s1 = 0.0f, s3 = 0.0f;
    #pragma unroll 4
    for (int it = 0; it < 16; it++) {
        int c = wid * 16 + it;
        size_t go = ((size_t)(b * 128 + c)) * 4096 + hw0 + 2 * lane;
        float2 z2 = *(const float2*)(batch + go);
        float q0 = qsT[c * 66 + 2 * lane];
        float q1 = qsT[c * 66 + 2 * lane + 1];
        float dq0 = q0 - z2.x, dq1 = q1 - z2.y;
        float ov0 = z2.x + dq0, ov1 = z2.y + dq1;
        float d30 = z2.x - ov0, d31 = z2.y - ov1;
        *(float2*)(out + go) = make_float2(ov0, ov1);
        s1 += dq0 * dq0 + dq1 * dq1;
        s3 += d30 * d30 + d31 * d31;
    }
    red[tid] = s1; red[256 + tid] = s3;
    __syncthreads();
    #pragma unroll
    for (int st = 128; st > 0; st >>= 1) {
        if (tid < st) { red[tid] += red[tid + st]; red[256 + tid] += red[256 + tid + st]; }
        __syncthreads();
    }
    if (tid == 0) {
        atomicAdd(&g_s1, (double)red[0]);
        atomicAdd(&g_s3, (double)red[256]);
    }
}

// ---------- finalize ----------
__global__ void vq_finalize(float* __restrict__ out, int out_size) {
    if (out_size <= TOT_ELEMS) return;
    const double inv = 1.0 / (double)TOT_ELEMS;
    float t1 = (float)(g_s1 * inv);
    float t3 = (float)(g_s3 * inv);
    out[TOT_ELEMS] = (t1 + t1) + t3 * 50.0f;
}

// ---------- launch ----------
extern "C" void kernel_launch(void* const* d_in, const int* in_sizes, int n_in,
                              void* d_out, int out_size) {
    const float* batch = (const float*)d_in[0];
    const float* wq    = (const float*)d_in[1];
    if (n_in >= 2 && in_sizes[0] == NUM_CODES * DIM) {
        const float* t = batch; batch = wq; wq = t;
    }
    float* out = (float*)d_out;

    cudaFuncSetAttribute(vq_tensor, cudaFuncAttributeMaxDynamicSharedMemorySize,
                         SMEM_TENSOR);

    vq_prep<<<320, 256>>>(wq);
    vq_tensor<<<N_TOKENS / TPC, 512, SMEM_TENSOR>>>(batch);
    vq_resolve<<<256, 256>>>(batch, wq);
    vq_fullB<<<32, 256>>>(batch, wq);
    vq_output<<<N_TOKENS / 64, 256>>>(batch, wq, out);
    vq_finalize<<<1, 1>>>(out, out_size);
}

// round 14
// speedup vs baseline: 4.5502x; 1.0831x over previous
#include <cuda_runtime.h>
#include <cuda_fp16.h>
#include <math_constants.h>

#define NUM_CODES 2560
#define DIM       128
#define N_TOKENS  65536
#define TOT_ELEMS 8388608
#define TPC       64          // tokens per CTA (tensor pass)
#define CPC       64
#define N_CHUNKS  40
#define NSTAGE    3

#define RS          272
#define STAGE_B     (64 * RS)                 // 17408
#define OFF_BST     0                          // B stages / A temp (aliased; A=64*RS=17408 <= stages)
#define OFF_ZN      (NSTAGE * STAGE_B)         // 52224 (64 floats)
#define OFF_CNT     (OFF_ZN + 256)             // 52480 (64 ints)
#define OFF_CAND    (OFF_CNT + 256)            // 52736 (64*16 u16 = 2048)
#define SMEM_TENSOR (OFF_CAND + 2048)          // 54784

__device__ __align__(16) float  g_enorm[NUM_CODES];
__device__ __align__(16) __half g_wh16[NUM_CODES * DIM];   // fp16(w * 4096)
__device__ int    g_enmax_i = 0;
__device__ int    g_inds[N_TOKENS];
__device__ int    g_tokA[N_TOKENS];                         // token | (cnt<<16)
__device__ __align__(16) unsigned short g_candA[N_TOKENS * 16];
__device__ int    g_listB[N_TOKENS];
__device__ int    g_nA, g_nB;
__device__ double g_s1, g_s3;

// ---------- helpers ----------
__device__ __forceinline__ unsigned smem_u32(const void* p) {
    unsigned a;
    asm("{ .reg .u64 t; cvta.to.shared.u64 t, %1; cvt.u32.u64 %0, t; }" : "=r"(a) : "l"(p));
    return a;
}
__device__ __forceinline__ unsigned lds32(unsigned a) {
    unsigned v;
    asm volatile("ld.shared.b32 %0, [%1];" : "=r"(v) : "r"(a));
    return v;
}
__device__ __forceinline__ void mma_f16(float* c, const unsigned* a,
                                        unsigned b0, unsigned b1) {
    asm volatile(
        "mma.sync.aligned.m16n8k16.row.col.f32.f16.f16.f32 "
        "{%0,%1,%2,%3}, {%4,%5,%6,%7}, {%8,%9}, {%0,%1,%2,%3};"
        : "+f"(c[0]), "+f"(c[1]), "+f"(c[2]), "+f"(c[3])
        : "r"(a[0]), "r"(a[1]), "r"(a[2]), "r"(a[3]), "r"(b0), "r"(b1));
}

// ---------- prep: enorm (+max) + fp16(w*4096) ----------
__global__ void vq_prep(const float* __restrict__ w) {
    int gtid = blockIdx.x * blockDim.x + threadIdx.x;
    if (gtid == 0) { g_s1 = 0.0; g_s3 = 0.0; g_nA = 0; g_nB = 0; }
    int gw = gtid >> 5, lane = threadIdx.x & 31;
    if (gw < NUM_CODES) {
        const float* row = w + (size_t)gw * DIM;
        float s = 0.0f;
        #pragma unroll
        for (int k = lane; k < DIM; k += 32) {
            float v = row[k];
            s = __fadd_rn(s, __fmul_rn(v, v));
        }
        #pragma unroll
        for (int off = 16; off > 0; off >>= 1) s += __shfl_xor_sync(~0u, s, off);
        if (lane == 0) {
            g_enorm[gw] = s;
            atomicMax(&g_enmax_i, __float_as_int(s));
        }
    }
    int stride = gridDim.x * blockDim.x;
    for (int i = gtid; i < NUM_CODES * DIM; i += stride)
        g_wh16[i] = __float2half_rn(w[i] * 4096.0f);
}

// ---------- tensor pass: 128 threads / 4 warps, warp tile 16 tokens x 64 codes ----------
__device__ __forceinline__ void issue_chunk(unsigned sb, int tid, int cn, int st) {
    const uint4* gh = ((const uint4*)g_wh16) + (size_t)cn * 1024;
    unsigned base = sb + OFF_BST + st * STAGE_B;
    #pragma unroll
    for (int i = 0; i < 8; i++) {
        int f = tid + i * 128;
        unsigned d = base + (f >> 4) * RS + (f & 15) * 16;
        asm volatile("cp.async.cg.shared.global [%0], [%1], 16;" :: "r"(d), "l"(gh + f));
    }
}

__global__ void __launch_bounds__(128, 4)
vq_tensor(const float* __restrict__ batch) {
    extern __shared__ char smem[];
    const unsigned sb = smem_u32(smem);
    float*          zn_s  = (float*)(smem + OFF_ZN);
    int*            scnt  = (int*)(smem + OFF_CNT);
    unsigned short* scand = (unsigned short*)(smem + OFF_CAND);

    const int tid = threadIdx.x, wid = tid >> 5, lane = tid & 31;
    const int n0 = blockIdx.x * TPC, b = n0 >> 12, hw0 = n0 & 4095;
    const float* zbase = batch + (size_t)b * (DIM * 4096) + hw0;
    const float enmax = __int_as_float(g_enmax_i);

    // prologue: threads 0-63: token tid: znorm (R1 order) + fp16(z*16) into A temp
    if (tid < TPC) {
        const float* zp = zbase + tid;
        float acc = 0.0f;
        #pragma unroll 4
        for (int c = 0; c < DIM; c += 2) {
            float z0 = zp[(size_t)c * 4096];
            float z1 = zp[(size_t)(c + 1) * 4096];
            acc = __fadd_rn(acc, __fmul_rn(z0, z0));
            acc = __fadd_rn(acc, __fmul_rn(z1, z1));
            __half h0 = __float2half_rn(z0 * 16.0f);
            __half h1 = __float2half_rn(z1 * 16.0f);
            unsigned hp = (unsigned)__half_as_ushort(h0) |
                          ((unsigned)__half_as_ushort(h1) << 16);
            *(unsigned*)(smem + OFF_BST + tid * RS + c * 2) = hp;
        }
        zn_s[tid] = acc;
        scnt[tid] = 0;
    }
    __syncthreads();

    // warp tile: tokens [wid*16, wid*16+16); lane row = lane>>2 -> tokens Rb, Rb+8
    const unsigned Rb = wid * 16 + (lane >> 2);
    const unsigned Cb = (lane & 3) * 2;
    unsigned Ah[8][4];
    #pragma unroll
    for (int ks = 0; ks < 8; ks++) {
        unsigned a = sb + OFF_BST + Rb * RS + (ks * 16 + Cb) * 2;
        Ah[ks][0] = lds32(a);
        Ah[ks][1] = lds32(a + 8 * RS);
        Ah[ks][2] = lds32(a + 16);
        Ah[ks][3] = lds32(a + 8 * RS + 16);
    }
    float znr[2], TT[2];
    #pragma unroll
    for (int j = 0; j < 2; j++) {
        znr[j] = zn_s[Rb + j * 8];
        TT[j]  = 2.0f * (1.0e-3f * sqrtf(znr[j] * enmax) + 6.0e-5f);
    }
    __syncthreads();   // A temp fully consumed before B stages overwrite it

    issue_chunk(sb, tid, 0, 0);
    asm volatile("cp.async.commit_group;" ::: "memory");
    issue_chunk(sb, tid, 1, 1);
    asm volatile("cp.async.commit_group;" ::: "memory");
    issue_chunk(sb, tid, 2, 2);
    asm volatile("cp.async.commit_group;" ::: "memory");

    float acc[8][4];
    #pragma unroll
    for (int nt = 0; nt < 8; nt++)
        #pragma unroll
        for (int q = 0; q < 4; q++) acc[nt][q] = 0.0f;

    float v1[2] = {CUDART_INF_F, CUDART_INF_F};

    const unsigned bfrag_base = sb + OFF_BST + (lane >> 2) * RS + Cb * 2;
    const float DS = -3.0517578125e-05f;   // -2 * 2^-16

    for (int cn = 0; cn < N_CHUNKS; cn++) {
        asm volatile("cp.async.wait_group 2;" ::: "memory");
        __syncthreads();
        const unsigned sbase = (unsigned)(cn % NSTAGE) * STAGE_B;

        #pragma unroll
        for (int ks = 0; ks < 8; ks++) {
            #pragma unroll
            for (int nt = 0; nt < 8; nt++) {
                unsigned ba = bfrag_base + sbase + nt * 8 * RS + ks * 32;
                unsigned b0 = lds32(ba), b1 = lds32(ba + 16);
                mma_f16(acc[nt], Ah[ks], b0, b1);
            }
        }
        __syncthreads();
        if (cn + NSTAGE < N_CHUNKS) issue_chunk(sb, tid, cn + NSTAGE, cn % NSTAGE);
        asm volatile("cp.async.commit_group;" ::: "memory");

        // ---- distances in place (enorm from L2 via __ldg) ----
        #pragma unroll
        for (int nt = 0; nt < 8; nt++) {
            const int code0 = cn * CPC + nt * 8 + (int)Cb;
            float2 e = __ldg((const float2*)(g_enorm + code0));
            acc[nt][0] = fmaf(DS, acc[nt][0], znr[0] + e.x);
            acc[nt][1] = fmaf(DS, acc[nt][1], znr[0] + e.y);
            acc[nt][2] = fmaf(DS, acc[nt][2], znr[1] + e.x);
            acc[nt][3] = fmaf(DS, acc[nt][3], znr[1] + e.y);
        }
        // ---- per slot: lane min -> quad (token-global) min -> collect ----
        #pragma unroll
        for (int sl = 0; sl < 2; sl++) {
            float m = fminf(acc[0][2 * sl], acc[0][2 * sl + 1]);
            #pragma unroll
            for (int nt = 1; nt < 8; nt++)
                m = fminf(m, fminf(acc[nt][2 * sl], acc[nt][2 * sl + 1]));
            float mq = m;
            mq = fminf(mq, __shfl_xor_sync(~0u, mq, 1));
            mq = fminf(mq, __shfl_xor_sync(~0u, mq, 2));
            v1[sl] = fminf(v1[sl], mq);
            float lim = v1[sl] + TT[sl];
            if (m < lim) {
                int tl = (int)Rb + sl * 8;
                #pragma unroll
                for (int nt = 0; nt < 8; nt++) {
                    int code0 = cn * CPC + nt * 8 + (int)Cb;
                    float dA = acc[nt][2 * sl];
                    float dB = acc[nt][2 * sl + 1];
                    if (dA < lim) {
                        int p = atomicAdd(&scnt[tl], 1);
                        if (p < 16) scand[tl * 16 + p] = (unsigned short)code0;
                    }
                    if (dB < lim) {
                        int p = atomicAdd(&scnt[tl], 1);
                        if (p < 16) scand[tl * 16 + p] = (unsigned short)(code0 + 1);
                    }
                }
            }
        }
        // ---- reset acc ----
        #pragma unroll
        for (int nt = 0; nt < 8; nt++) {
            acc[nt][0] = 0.0f; acc[nt][1] = 0.0f;
            acc[nt][2] = 0.0f; acc[nt][3] = 0.0f;
        }
    }

    // ---- finale: classify per token ----
    __syncthreads();
    if (tid < TPC) {
        int c = scnt[tid];
        int token = n0 + tid;
        if (c == 1) {
            g_inds[token] = scand[tid * 16];
        } else if (c <= 16) {
            int p = atomicAdd(&g_nA, 1);
            g_tokA[p] = token | (c << 16);
            for (int i = 0; i < c; i++)
                g_candA[p * 16 + i] = scand[tid * 16 + i];
        } else {
            int p = atomicAdd(&g_nB, 1);
            g_listB[p] = token;
        }
    }
}

// ---------- resolve: exact R1-numerics over collected candidates ----------
__global__ void __launch_bounds__(256, 1)
vq_resolve(const float* __restrict__ batch, const float* __restrict__ w) {
    const int nA = *(volatile int*)&g_nA;
    for (int k = blockIdx.x * 256 + threadIdx.x; k < nA; k += gridDim.x * 256) {
        int word = g_tokA[k];
        int token = word & 0xFFFF;
        int cnt = word >> 16;
        const float* zp = batch + (size_t)(token >> 12) * (DIM * 4096) + (token & 4095);

        float zn = 0.0f;
        #pragma unroll 4
        for (int c = 0; c < DIM; c += 2) {
            float z0 = zp[(size_t)c * 4096];
            float z1 = zp[(size_t)(c + 1) * 4096];
            zn = __fadd_rn(zn, __fmul_rn(z0, z0));
            zn = __fadd_rn(zn, __fmul_rn(z1, z1));
        }

        float bv = CUDART_INF_F;
        int   bi = 0x7FFFFFFF;
        for (int base = 0; base < cnt; base += 4) {
            int nc = cnt - base; if (nc > 4) nc = 4;
            int idx[4];
            const float* wr[4];
            float lo[4] = {0.f, 0.f, 0.f, 0.f}, hi[4] = {0.f, 0.f, 0.f, 0.f};
            #pragma unroll
            for (int q = 0; q < 4; q++) {
                idx[q] = g_candA[k * 16 + base + ((q < nc) ? q : 0)];
                wr[q] = w + (size_t)idx[q] * DIM;
            }
            #pragma unroll 2
            for (int c = 0; c < DIM; c += 2) {
                float z0 = zp[(size_t)c * 4096];
                float z1 = zp[(size_t)(c + 1) * 4096];
                #pragma unroll
                for (int q = 0; q < 4; q++) {
                    lo[q] = fmaf(z0, __ldg(&wr[q][c]), lo[q]);       // R1 even chain
                    hi[q] = fmaf(z1, __ldg(&wr[q][c + 1]), hi[q]);   // R1 odd chain
                }
            }
            for (int q = 0; q < nc; q++) {
                float d = fmaf(-2.0f, __fadd_rn(lo[q], hi[q]),
                               __fadd_rn(zn, g_enorm[idx[q]]));
                if (d < bv || (d == bv && idx[q] < bi)) { bv = d; bi = idx[q]; }
            }
        }
        g_inds[token] = bi;
    }
}

// ---------- fullB: warp-per-token exact full scan (overflow only) ----------
__global__ void __launch_bounds__(256, 1)
vq_fullB(const float* __restrict__ batch, const float* __restrict__ w) {
    const int nB = *(volatile int*)&g_nB;
    __shared__ float zsm[8][128];

    const int tid = threadIdx.x, wid = tid >> 5, lane = tid & 31;

    for (int k = blockIdx.x * 8 + wid; k < nB; k += gridDim.x * 8) {
        int token = g_listB[k];
        const float* zp = batch + (size_t)(token >> 12) * (DIM * 4096) + (token & 4095);
        #pragma unroll
        for (int c = lane; c < DIM; c += 32)
            zsm[wid][c] = zp[(size_t)c * 4096];
        __syncwarp();

        float zn = 0.0f;
        #pragma unroll 8
        for (int c = 0; c < DIM; c++)
            zn = __fadd_rn(zn, __fmul_rn(zsm[wid][c], zsm[wid][c]));

        float bv = CUDART_INF_F;
        int   bi = 0;
        for (int kk = 0; kk < NUM_CODES / 32; kk++) {
            int code = lane + kk * 32;
            const float* wr = w + (size_t)code * DIM;
            float lo = 0.0f, hi = 0.0f;
            #pragma unroll 8
            for (int c = 0; c < DIM; c += 4) {
                lo = fmaf(zsm[wid][c],     __ldg(&wr[c]),     lo);
                hi = fmaf(zsm[wid][c + 1], __ldg(&wr[c + 1]), hi);
                lo = fmaf(zsm[wid][c + 2], __ldg(&wr[c + 2]), lo);
                hi = fmaf(zsm[wid][c + 3], __ldg(&wr[c + 3]), hi);
            }
            float dis = fmaf(-2.0f, __fadd_rn(lo, hi), __fadd_rn(zn, __ldg(&g_enorm[code])));
            if (dis < bv) { bv = dis; bi = code; }
        }
        #pragma unroll
        for (int off = 16; off > 0; off >>= 1) {
            float ov = __shfl_xor_sync(~0u, bv, off);
            int   oi = __shfl_xor_sync(~0u, bi, off);
            if (ov < bv || (ov == bv && oi < bi)) { bv = ov; bi = oi; }
        }
        if (lane == 0) g_inds[token] = bi;
        __syncwarp();
    }
}

// ---------- output + loss ----------
__global__ void __launch_bounds__(256, 1)
vq_output(const float* __restrict__ batch, const float* __restrict__ w,
          float* __restrict__ out) {
    __shared__ float qsT[128 * 66];
    __shared__ int   si[64];
    __shared__ float red[512];

    const int tid = threadIdx.x, wid = tid >> 5, lane = tid & 31;
    const int n0 = blockIdx.x * 64, b = n0 >> 12, hw0 = n0 & 4095;

    if (tid < 64) si[tid] = g_inds[n0 + tid];
    __syncthreads();

    const float4* w4 = (const float4*)w;
    #pragma unroll
    for (int k = 0; k < 8; k++) {
        int f = tid + k * 256;
        int r = f >> 5, c4 = f & 31;
        float4 v = __ldg(&w4[(size_t)si[r] * 32 + c4]);
        int cb = c4 * 4;
        qsT[(cb + 0) * 66 + r] = v.x;
        qsT[(cb + 1) * 66 + r] = v.y;
        qsT[(cb + 2) * 66 + r] = v.z;
        qsT[(cb + 3) * 66 + r] = v.w;
    }
    __syncthreads();

    float s1 = 0.0f, s3 = 0.0f;
    #pragma unroll 4
    for (int it = 0; it < 16; it++) {
        int c = wid * 16 + it;
        size_t go = ((size_t)(b * 128 + c)) * 4096 + hw0 + 2 * lane;
        float2 z2 = *(const float2*)(batch + go);
        float q0 = qsT[c * 66 + 2 * lane];
        float q1 = qsT[c * 66 + 2 * lane + 1];
        float dq0 = q0 - z2.x, dq1 = q1 - z2.y;
        float ov0 = z2.x + dq0, ov1 = z2.y + dq1;
        float d30 = z2.x - ov0, d31 = z2.y - ov1;
        *(float2*)(out + go) = make_float2(ov0, ov1);
        s1 += dq0 * dq0 + dq1 * dq1;
        s3 += d30 * d30 + d31 * d31;
    }
    red[tid] = s1; red[256 + tid] = s3;
    __syncthreads();
    #pragma unroll
    for (int st = 128; st > 0; st >>= 1) {
        if (tid < st) { red[tid] += red[tid + st]; red[256 + tid] += red[256 + tid + st]; }
        __syncthreads();
    }
    if (tid == 0) {
        atomicAdd(&g_s1, (double)red[0]);
        atomicAdd(&g_s3, (double)red[256]);
    }
}

// ---------- finalize ----------
__global__ void vq_finalize(float* __restrict__ out, int out_size) {
    if (out_size <= TOT_ELEMS) return;
    const double inv = 1.0 / (double)TOT_ELEMS;
    float t1 = (float)(g_s1 * inv);
    float t3 = (float)(g_s3 * inv);
    out[TOT_ELEMS] = (t1 + t1) + t3 * 50.0f;
}

// ---------- launch ----------
extern "C" void kernel_launch(void* const* d_in, const int* in_sizes, int n_in,
                              void* d_out, int out_size) {
    const float* batch = (const float*)d_in[0];
    const float* wq    = (const float*)d_in[1];
    if (n_in >= 2 && in_sizes[0] == NUM_CODES * DIM) {
        const float* t = batch; batch = wq; wq = t;
    }
    float* out = (float*)d_out;

    cudaFuncSetAttribute(vq_tensor, cudaFuncAttributeMaxDynamicSharedMemorySize,
                         SMEM_TENSOR);

    vq_prep<<<320, 256>>>(wq);
    vq_tensor<<<N_TOKENS / TPC, 128, SMEM_TENSOR>>>(batch);
    vq_resolve<<<256, 256>>>(batch, wq);
    vq_fullB<<<32, 256>>>(batch, wq);
    vq_output<<<N_TOKENS / 64, 256>>>(batch, wq, out);
    vq_finalize<<<1, 1>>>(out, out_size);
}